// round 1
// baseline (speedup 1.0000x reference)
#include <cuda_runtime.h>
#include <cuda_fp16.h>
#include <cstdint>

#define TTOK 8192
#define DIMX 1024
#define HIDX 2816
#define NE 8
#define NEX 9          // 8 routed experts + shared expert as expert 8
#define CAP 8192
#define HD (HIDX*DIMX) // 2883584

// ---------------- scratch (static device globals; no allocations) -------------
__device__ __half g_x16[(size_t)TTOK*DIMX];          // x in fp16
__device__ __half g_wg[(size_t)NEX*HD];              // gate weights [9][H][D]
__device__ __half g_wu[(size_t)NEX*HD];              // up weights   [9][H][D]
__device__ __half g_wd[(size_t)NEX*HD];              // down weights [9][D][H]
__device__ __half g_h16[(size_t)NEX*CAP*HIDX];       // hidden activations
__device__ int    g_cnt[NEX];
__device__ int    g_tok[NEX*CAP];
__device__ float  g_twf[NEX*CAP];

// ---------------- small helpers ----------------------------------------------
__device__ __forceinline__ uint32_t sptr(const void* p){
  return (uint32_t)__cvta_generic_to_shared(p);
}
__device__ __forceinline__ void cpasync16(uint32_t dst, const void* src){
  asm volatile("cp.async.cg.shared.global [%0], [%1], 16;\n" :: "r"(dst), "l"(src));
}
__device__ __forceinline__ void cpcommit(){ asm volatile("cp.async.commit_group;\n"); }
template<int N> __device__ __forceinline__ void cpwait(){
  asm volatile("cp.async.wait_group %0;\n" :: "n"(N));
}
__device__ __forceinline__ void ldm4(uint32_t &r0,uint32_t &r1,uint32_t &r2,uint32_t &r3,uint32_t addr){
  asm volatile("ldmatrix.sync.aligned.m8n8.x4.shared.b16 {%0,%1,%2,%3}, [%4];\n"
    : "=r"(r0),"=r"(r1),"=r"(r2),"=r"(r3) : "r"(addr));
}
__device__ __forceinline__ void mma16816(float&d0,float&d1,float&d2,float&d3,
   uint32_t a0,uint32_t a1,uint32_t a2,uint32_t a3,uint32_t b0,uint32_t b1){
  asm volatile("mma.sync.aligned.m16n8k16.row.col.f32.f16.f16.f32 "
    "{%0,%1,%2,%3},{%4,%5,%6,%7},{%8,%9},{%0,%1,%2,%3};\n"
    : "+f"(d0),"+f"(d1),"+f"(d2),"+f"(d3)
    : "r"(a0),"r"(a1),"r"(a2),"r"(a3),"r"(b0),"r"(b1));
}
// XOR swizzle: 16B chunks within a 32-half row; conflict-free for ldmatrix
// (phys chunk = ch ^ ((row>>1)&3) makes all 8 rows of a phase hit distinct
//  16B bank groups given the 64B row stride).
__device__ __forceinline__ int swz(int row, int ch){
  return row*32 + ((ch ^ ((row>>1)&3))<<3);
}

// ---------------- conversion fp32 -> fp16 -------------------------------------
__global__ void cvt_seg(const float* __restrict__ src, int seg, int n4){
  int i = blockIdx.x*blockDim.x + threadIdx.x;
  if (i >= n4) return;
  __half* dst;
  switch(seg){
    case 0: dst = g_x16; break;
    case 1: dst = g_wg;  break;
    case 2: dst = g_wu;  break;
    case 3: dst = g_wd;  break;
    case 4: dst = g_wg + (size_t)NE*HD; break;
    case 5: dst = g_wu + (size_t)NE*HD; break;
    default: dst = g_wd + (size_t)NE*HD; break;
  }
  float4 v = reinterpret_cast<const float4*>(src)[i];
  __half2* d2 = reinterpret_cast<__half2*>(dst) + 2*(size_t)i;
  d2[0] = __floats2half2_rn(v.x, v.y);
  d2[1] = __floats2half2_rn(v.z, v.w);
}

// ---------------- init: counts + shared-expert identity list ------------------
__global__ void init_k(){
  int i = blockIdx.x*blockDim.x + threadIdx.x;
  if (i < NE)  g_cnt[i] = 0;
  if (i == NE) g_cnt[NE] = TTOK;
  if (i < TTOK){ g_tok[NE*CAP+i] = i; g_twf[NE*CAP+i] = 1.0f; }
}

__global__ void zero_k(float4* __restrict__ out, int n4){
  int i = blockIdx.x*blockDim.x + threadIdx.x;
  if (i < n4) out[i] = make_float4(0.f,0.f,0.f,0.f);
}

// ---------------- router: warp per token, sigmoid top-2, scatter --------------
__global__ void router_k(const float* __restrict__ x, const float* __restrict__ rw,
                         const float* __restrict__ eb){
  int t = blockIdx.x*8 + (threadIdx.x>>5);
  int lane = threadIdx.x & 31;
  if (t >= TTOK) return;
  const float* xr = x + (size_t)t*DIMX;
  float acc[NE];
  #pragma unroll
  for (int e=0;e<NE;e++) acc[e]=0.f;
  for (int k = lane; k < DIMX; k += 32){
    float xv = xr[k];
    #pragma unroll
    for (int e=0;e<NE;e++) acc[e] = fmaf(xv, rw[e*DIMX+k], acc[e]);
  }
  #pragma unroll
  for (int e=0;e<NE;e++){
    #pragma unroll
    for (int o=16;o>0;o>>=1) acc[e] += __shfl_xor_sync(0xffffffffu, acc[e], o);
  }
  if (lane==0){
    float s[NE];
    #pragma unroll
    for (int e=0;e<NE;e++){
      float l = acc[e] + eb[e];
      s[e] = 1.f / (1.f + __expf(-l));
    }
    int i0=0;
    #pragma unroll
    for (int e=1;e<NE;e++) if (s[e] > s[i0]) i0=e;
    int i1 = (i0==0)?1:0;
    #pragma unroll
    for (int e=0;e<NE;e++) if (e!=i0 && s[e] > s[i1]) i1=e;
    float inv = 1.f / (s[i0]+s[i1]+1e-6f);
    int p0 = atomicAdd(&g_cnt[i0], 1);
    g_tok[i0*CAP+p0]=t; g_twf[i0*CAP+p0]=s[i0]*inv;
    int p1 = atomicAdd(&g_cnt[i1], 1);
    g_tok[i1*CAP+p1]=t; g_twf[i1*CAP+p1]=s[i1]*inv;
  }
}

// ---------------- GEMM 1: hidden = silu(X Gᵀ) * (X Uᵀ)   (fused dual-B) ------
// BM=128, BN=64, BK=32, 256 thr (8 warps as 4m x 2n), 2-stage cp.async pipeline.
__global__ __launch_bounds__(256,1) void gemm_gateup(){
  const int e = blockIdx.z;
  const int cntE = g_cnt[e];
  const int rowBase = blockIdx.x * 128;
  if (rowBase >= cntE) return;
  const int nBase = blockIdx.y * 64;

  __shared__ __half As[2][128*32];
  __shared__ __half Bgs[2][64*32];
  __shared__ __half Bus[2][64*32];

  const int tid  = threadIdx.x;
  const int lane = tid & 31;
  const int warp = tid >> 5;
  const int wm   = warp >> 1;   // 0..3
  const int wn   = warp & 1;    // 0..1

  const __half* __restrict__ Wg = g_wg + (size_t)e*HD + (size_t)nBase*DIMX;
  const __half* __restrict__ Wu = g_wu + (size_t)e*HD + (size_t)nBase*DIMX;
  const int* __restrict__ tokp = g_tok + e*CAP + rowBase;

  const int arow = tid >> 2;           // rows arow and arow+64
  const int ach  = tid & 3;
  const int tk0 = (rowBase + arow      < cntE) ? tokp[arow]    : 0;
  const int tk1 = (rowBase + arow + 64 < cntE) ? tokp[arow+64] : 0;

  const uint32_t sA  = sptr(&As[0][0]);
  const uint32_t sBg = sptr(&Bgs[0][0]);
  const uint32_t sBu = sptr(&Bus[0][0]);

  auto load_stage = [&](int buf, int k0){
    cpasync16(sA + (uint32_t)(buf*128*32 + swz(arow,    ach))*2,
              g_x16 + (size_t)tk0*DIMX + k0 + ach*8);
    cpasync16(sA + (uint32_t)(buf*128*32 + swz(arow+64, ach))*2,
              g_x16 + (size_t)tk1*DIMX + k0 + ach*8);
    uint32_t db = (uint32_t)(buf*64*32 + swz(arow, ach))*2;
    cpasync16(sBg + db, Wg + (size_t)arow*DIMX + k0 + ach*8);
    cpasync16(sBu + db, Wu + (size_t)arow*DIMX + k0 + ach*8);
  };

  float accG[2][4][4], accU[2][4][4];
  #pragma unroll
  for (int i=0;i<2;i++)
    #pragma unroll
    for (int j=0;j<4;j++)
      #pragma unroll
      for (int k=0;k<4;k++){ accG[i][j][k]=0.f; accU[i][j][k]=0.f; }

  load_stage(0, 0);
  cpcommit();

  const int KT = DIMX/32;
  for (int kt=0; kt<KT; ++kt){
    if (kt+1 < KT){ load_stage((kt+1)&1, (kt+1)*32); cpcommit(); cpwait<1>(); }
    else          { cpwait<0>(); }
    __syncthreads();
    const int buf = kt & 1;
    const uint32_t baseA = sA  + (uint32_t)buf*128*32*2;
    const uint32_t baseG = sBg + (uint32_t)buf*64*32*2;
    const uint32_t baseU = sBu + (uint32_t)buf*64*32*2;
    #pragma unroll
    for (int ks=0; ks<2; ++ks){
      uint32_t a[2][4];
      #pragma unroll
      for (int mt=0; mt<2; ++mt){
        int r  = wm*32 + mt*16 + (lane&15);
        int ch = ks*2 + (lane>>4);
        ldm4(a[mt][0],a[mt][1],a[mt][2],a[mt][3], baseA + (uint32_t)swz(r,ch)*2);
      }
      uint32_t bg[2][4], bu[2][4];
      #pragma unroll
      for (int np=0; np<2; ++np){
        int r  = wn*32 + np*16 + (lane&7) + (lane>>4)*8;
        int ch = ks*2 + ((lane>>3)&1);
        uint32_t off = (uint32_t)swz(r,ch)*2;
        ldm4(bg[np][0],bg[np][1],bg[np][2],bg[np][3], baseG + off);
        ldm4(bu[np][0],bu[np][1],bu[np][2],bu[np][3], baseU + off);
      }
      #pragma unroll
      for (int mt=0; mt<2; ++mt){
        #pragma unroll
        for (int nt=0; nt<4; ++nt){
          int np = nt>>1, p = (nt&1)*2;
          mma16816(accG[mt][nt][0],accG[mt][nt][1],accG[mt][nt][2],accG[mt][nt][3],
                   a[mt][0],a[mt][1],a[mt][2],a[mt][3], bg[np][p], bg[np][p+1]);
          mma16816(accU[mt][nt][0],accU[mt][nt][1],accU[mt][nt][2],accU[mt][nt][3],
                   a[mt][0],a[mt][1],a[mt][2],a[mt][3], bu[np][p], bu[np][p+1]);
        }
      }
    }
    __syncthreads();
  }

  // epilogue: silu(g)*u -> fp16 hidden scratch (unconditional; padded rows harmless)
  const int r0 = lane>>2, c0 = (lane&3)*2;
  #pragma unroll
  for (int mt=0; mt<2; ++mt){
    #pragma unroll
    for (int hh=0; hh<2; ++hh){
      int slot = rowBase + wm*32 + mt*16 + r0 + hh*8;
      __half2* hrow = reinterpret_cast<__half2*>(g_h16 + ((size_t)e*CAP + slot)*HIDX);
      #pragma unroll
      for (int nt=0; nt<4; ++nt){
        float gv0 = accG[mt][nt][hh*2+0], gv1 = accG[mt][nt][hh*2+1];
        float uv0 = accU[mt][nt][hh*2+0], uv1 = accU[mt][nt][hh*2+1];
        float h0 = gv0 / (1.f + __expf(-gv0)) * uv0;
        float h1 = gv1 / (1.f + __expf(-gv1)) * uv1;
        int gc = nBase + wn*32 + nt*8 + c0;
        hrow[gc>>1] = __floats2half2_rn(h0, h1);
      }
    }
  }
}

// ---------------- GEMM 2: out += w * (hidden Dᵀ)  (atomic scatter) ------------
__global__ __launch_bounds__(256,1) void gemm_down(float* __restrict__ out){
  const int e = blockIdx.z;
  const int cntE = g_cnt[e];
  const int rowBase = blockIdx.x * 128;
  if (rowBase >= cntE) return;
  const int nBase = blockIdx.y * 64;   // over DIM

  __shared__ __half As[2][128*32];
  __shared__ __half Bs[2][64*32];

  const int tid  = threadIdx.x;
  const int lane = tid & 31;
  const int warp = tid >> 5;
  const int wm   = warp >> 1;
  const int wn   = warp & 1;

  const __half* __restrict__ Ab = g_h16 + ((size_t)e*CAP + rowBase)*HIDX;
  const __half* __restrict__ Wd = g_wd + (size_t)e*HD + (size_t)nBase*HIDX;

  const int arow = tid >> 2;
  const int ach  = tid & 3;

  const uint32_t sA = sptr(&As[0][0]);
  const uint32_t sB = sptr(&Bs[0][0]);

  auto load_stage = [&](int buf, int k0){
    cpasync16(sA + (uint32_t)(buf*128*32 + swz(arow,    ach))*2,
              Ab + (size_t)arow*HIDX + k0 + ach*8);
    cpasync16(sA + (uint32_t)(buf*128*32 + swz(arow+64, ach))*2,
              Ab + (size_t)(arow+64)*HIDX + k0 + ach*8);
    cpasync16(sB + (uint32_t)(buf*64*32 + swz(arow, ach))*2,
              Wd + (size_t)arow*HIDX + k0 + ach*8);
  };

  float acc[2][4][4];
  #pragma unroll
  for (int i=0;i<2;i++)
    #pragma unroll
    for (int j=0;j<4;j++)
      #pragma unroll
      for (int k=0;k<4;k++) acc[i][j][k]=0.f;

  load_stage(0, 0);
  cpcommit();

  const int KT = HIDX/32;   // 88
  for (int kt=0; kt<KT; ++kt){
    if (kt+1 < KT){ load_stage((kt+1)&1, (kt+1)*32); cpcommit(); cpwait<1>(); }
    else          { cpwait<0>(); }
    __syncthreads();
    const int buf = kt & 1;
    const uint32_t baseA = sA + (uint32_t)buf*128*32*2;
    const uint32_t baseB = sB + (uint32_t)buf*64*32*2;
    #pragma unroll
    for (int ks=0; ks<2; ++ks){
      uint32_t a[2][4];
      #pragma unroll
      for (int mt=0; mt<2; ++mt){
        int r  = wm*32 + mt*16 + (lane&15);
        int ch = ks*2 + (lane>>4);
        ldm4(a[mt][0],a[mt][1],a[mt][2],a[mt][3], baseA + (uint32_t)swz(r,ch)*2);
      }
      uint32_t b[2][4];
      #pragma unroll
      for (int np=0; np<2; ++np){
        int r  = wn*32 + np*16 + (lane&7) + (lane>>4)*8;
        int ch = ks*2 + ((lane>>3)&1);
        ldm4(b[np][0],b[np][1],b[np][2],b[np][3], baseB + (uint32_t)swz(r,ch)*2);
      }
      #pragma unroll
      for (int mt=0; mt<2; ++mt){
        #pragma unroll
        for (int nt=0; nt<4; ++nt){
          int np = nt>>1, p = (nt&1)*2;
          mma16816(acc[mt][nt][0],acc[mt][nt][1],acc[mt][nt][2],acc[mt][nt][3],
                   a[mt][0],a[mt][1],a[mt][2],a[mt][3], b[np][p], b[np][p+1]);
        }
      }
    }
    __syncthreads();
  }

  // epilogue: scale by routing weight, atomic scatter-add into out
  const int r0 = lane>>2, c0 = (lane&3)*2;
  #pragma unroll
  for (int mt=0; mt<2; ++mt){
    #pragma unroll
    for (int hh=0; hh<2; ++hh){
      int slot = rowBase + wm*32 + mt*16 + r0 + hh*8;
      if (slot < cntE){
        int   tk = g_tok[e*CAP+slot];
        float w  = g_twf[e*CAP+slot];
        float* orow = out + (size_t)tk*DIMX;
        #pragma unroll
        for (int nt=0; nt<4; ++nt){
          int gc = nBase + wn*32 + nt*8 + c0;
          atomicAdd(orow + gc,     acc[mt][nt][hh*2+0]*w);
          atomicAdd(orow + gc + 1, acc[mt][nt][hh*2+1]*w);
        }
      }
    }
  }
}

// ---------------- launch ------------------------------------------------------
extern "C" void kernel_launch(void* const* d_in, const int* in_sizes, int n_in,
                              void* d_out, int out_size){
  const float* x  = (const float*)d_in[0];
  const float* rw = (const float*)d_in[1];
  const float* eb = (const float*)d_in[2];
  const float* gw = (const float*)d_in[3];
  const float* uw = (const float*)d_in[4];
  const float* dw = (const float*)d_in[5];
  const float* sg = (const float*)d_in[6];
  const float* su = (const float*)d_in[7];
  const float* sd = (const float*)d_in[8];
  float* out = (float*)d_out;
  (void)in_sizes; (void)n_in; (void)out_size;

  auto cvt = [&](const float* s, int seg, long n){
    int n4 = (int)(n/4);
    cvt_seg<<<(n4+255)/256, 256>>>(s, seg, n4);
  };
  cvt(x,  0, (long)TTOK*DIMX);
  cvt(gw, 1, (long)NE*HD);
  cvt(uw, 2, (long)NE*HD);
  cvt(dw, 3, (long)NE*HD);
  cvt(sg, 4, (long)HD);
  cvt(su, 5, (long)HD);
  cvt(sd, 6, (long)HD);

  init_k<<<TTOK/256, 256>>>();
  zero_k<<<(TTOK*DIMX/4 + 255)/256, 256>>>((float4*)out, TTOK*DIMX/4);
  router_k<<<TTOK/8, 256>>>(x, rw, eb);

  gemm_gateup<<<dim3(TTOK/128, HIDX/64, NEX), 256>>>();
  gemm_down  <<<dim3(TTOK/128, DIMX/64, NEX), 256>>>(out);
}

// round 2
// speedup vs baseline: 1.1277x; 1.1277x over previous
#include <cuda_runtime.h>
#include <cuda_fp16.h>
#include <cstdint>

#define TTOK 8192
#define DIMX 1024
#define HIDX 2816
#define NE 8
#define NEX 9          // 8 routed experts + shared expert as expert 8
#define CAP 8192
#define HD (HIDX*DIMX) // 2883584

// ---------------- scratch (static device globals; no allocations) -------------
__device__ __half g_x16[(size_t)TTOK*DIMX];          // x in fp16
__device__ __half g_wg[(size_t)NEX*HD];              // gate weights [9][H][D]
__device__ __half g_wu[(size_t)NEX*HD];              // up weights   [9][H][D]
__device__ __half g_wd[(size_t)NEX*HD];              // down weights [9][D][H]
__device__ __half g_h16[(size_t)NEX*CAP*HIDX];       // hidden activations
__device__ float  g_y[(size_t)NEX*CAP*DIMX];         // per-(expert,slot) outputs
__device__ int    g_cnt[NEX];
__device__ int    g_tok[NEX*CAP];
__device__ float  g_twf[NEX*CAP];
__device__ int    g_pos[2*TTOK];                     // token -> (e*CAP+slot) x2

// ---------------- small helpers ----------------------------------------------
__device__ __forceinline__ uint32_t sptr(const void* p){
  return (uint32_t)__cvta_generic_to_shared(p);
}
__device__ __forceinline__ void cpasync16(uint32_t dst, const void* src){
  asm volatile("cp.async.cg.shared.global [%0], [%1], 16;\n" :: "r"(dst), "l"(src));
}
__device__ __forceinline__ void cpcommit(){ asm volatile("cp.async.commit_group;\n"); }
template<int N> __device__ __forceinline__ void cpwait(){
  asm volatile("cp.async.wait_group %0;\n" :: "n"(N));
}
__device__ __forceinline__ void ldm4(uint32_t &r0,uint32_t &r1,uint32_t &r2,uint32_t &r3,uint32_t addr){
  asm volatile("ldmatrix.sync.aligned.m8n8.x4.shared.b16 {%0,%1,%2,%3}, [%4];\n"
    : "=r"(r0),"=r"(r1),"=r"(r2),"=r"(r3) : "r"(addr));
}
__device__ __forceinline__ void mma16816(float&d0,float&d1,float&d2,float&d3,
   uint32_t a0,uint32_t a1,uint32_t a2,uint32_t a3,uint32_t b0,uint32_t b1){
  asm volatile("mma.sync.aligned.m16n8k16.row.col.f32.f16.f16.f32 "
    "{%0,%1,%2,%3},{%4,%5,%6,%7},{%8,%9},{%0,%1,%2,%3};\n"
    : "+f"(d0),"+f"(d1),"+f"(d2),"+f"(d3)
    : "r"(a0),"r"(a1),"r"(a2),"r"(a3),"r"(b0),"r"(b1));
}
// XOR swizzle: 16B chunks within a 32-half row; conflict-free for ldmatrix.
__device__ __forceinline__ int swz(int row, int ch){
  return row*32 + ((ch ^ ((row>>1)&3))<<3);
}

// ---------------- conversion fp32 -> fp16 -------------------------------------
__global__ void cvt_seg(const float* __restrict__ src, int seg, int n4){
  int i = blockIdx.x*blockDim.x + threadIdx.x;
  if (i >= n4) return;
  __half* dst;
  switch(seg){
    case 0: dst = g_x16; break;
    case 1: dst = g_wg;  break;
    case 2: dst = g_wu;  break;
    case 3: dst = g_wd;  break;
    case 4: dst = g_wg + (size_t)NE*HD; break;
    case 5: dst = g_wu + (size_t)NE*HD; break;
    default: dst = g_wd + (size_t)NE*HD; break;
  }
  float4 v = reinterpret_cast<const float4*>(src)[i];
  __half2* d2 = reinterpret_cast<__half2*>(dst) + 2*(size_t)i;
  d2[0] = __floats2half2_rn(v.x, v.y);
  d2[1] = __floats2half2_rn(v.z, v.w);
}

// ---------------- init: counts + shared-expert identity list ------------------
__global__ void init_k(){
  int i = blockIdx.x*blockDim.x + threadIdx.x;
  if (i < NE)  g_cnt[i] = 0;
  if (i == NE) g_cnt[NE] = TTOK;
  if (i < TTOK){ g_tok[NE*CAP+i] = i; g_twf[NE*CAP+i] = 1.0f; }
}

// ---------------- router: warp per token, sigmoid top-2, scatter --------------
__global__ void router_k(const float* __restrict__ x, const float* __restrict__ rw,
                         const float* __restrict__ eb){
  int t = blockIdx.x*8 + (threadIdx.x>>5);
  int lane = threadIdx.x & 31;
  if (t >= TTOK) return;
  const float* xr = x + (size_t)t*DIMX;
  float acc[NE];
  #pragma unroll
  for (int e=0;e<NE;e++) acc[e]=0.f;
  for (int k = lane; k < DIMX; k += 32){
    float xv = xr[k];
    #pragma unroll
    for (int e=0;e<NE;e++) acc[e] = fmaf(xv, rw[e*DIMX+k], acc[e]);
  }
  #pragma unroll
  for (int e=0;e<NE;e++){
    #pragma unroll
    for (int o=16;o>0;o>>=1) acc[e] += __shfl_xor_sync(0xffffffffu, acc[e], o);
  }
  if (lane==0){
    float s[NE];
    #pragma unroll
    for (int e=0;e<NE;e++){
      float l = acc[e] + eb[e];
      s[e] = 1.f / (1.f + __expf(-l));
    }
    int i0=0;
    #pragma unroll
    for (int e=1;e<NE;e++) if (s[e] > s[i0]) i0=e;
    int i1 = (i0==0)?1:0;
    #pragma unroll
    for (int e=0;e<NE;e++) if (e!=i0 && s[e] > s[i1]) i1=e;
    float inv = 1.f / (s[i0]+s[i1]+1e-6f);
    int p0 = atomicAdd(&g_cnt[i0], 1);
    g_tok[i0*CAP+p0]=t; g_twf[i0*CAP+p0]=s[i0]*inv; g_pos[2*t]   = i0*CAP+p0;
    int p1 = atomicAdd(&g_cnt[i1], 1);
    g_tok[i1*CAP+p1]=t; g_twf[i1*CAP+p1]=s[i1]*inv; g_pos[2*t+1] = i1*CAP+p1;
  }
}

// =============== GEMM 1: hidden = silu(X Gᵀ) * (X Uᵀ) =========================
// BM=256, BN=64(dual G/U), BK=32, 256 thr (8 m-warps), 3-stage cp.async pipeline.
#define GU_STAGE (256*32 + 64*32 + 64*32)   // halves per stage = 12288
__global__ __launch_bounds__(256,1) void gemm_gateup(){
  extern __shared__ __half sm[];
  const int e = blockIdx.z;
  const int cntE = g_cnt[e];
  const int rowBase = blockIdx.x * 256;
  if (rowBase >= cntE) return;
  const int nBase = blockIdx.y * 64;

  const int tid  = threadIdx.x;
  const int lane = tid & 31;
  const int wm   = tid >> 5;          // 8 m-warps, 32 rows each

  const __half* __restrict__ Wg = g_wg + (size_t)e*HD + (size_t)nBase*DIMX;
  const __half* __restrict__ Wu = g_wu + (size_t)e*HD + (size_t)nBase*DIMX;
  const int* __restrict__ tokp = g_tok + e*CAP + rowBase;

  const int lrow = tid >> 2;          // 0..63
  const int lch  = tid & 3;
  int tk[4];
  #pragma unroll
  for (int i=0;i<4;i++){
    int r = lrow + i*64;
    tk[i] = (rowBase + r < cntE) ? tokp[r] : 0;
  }

  const uint32_t sA  = sptr(sm);                       // [3][256*32]
  const uint32_t sBg = sA  + (uint32_t)3*256*32*2;     // [3][64*32]
  const uint32_t sBu = sBg + (uint32_t)3*64*32*2;      // [3][64*32]

  auto load_stage = [&](int buf, int k0){
    #pragma unroll
    for (int i=0;i<4;i++)
      cpasync16(sA + (uint32_t)(buf*256*32 + swz(lrow+i*64, lch))*2,
                g_x16 + (size_t)tk[i]*DIMX + k0 + lch*8);
    uint32_t db = (uint32_t)(buf*64*32 + swz(lrow, lch))*2;
    cpasync16(sBg + db, Wg + (size_t)lrow*DIMX + k0 + lch*8);
    cpasync16(sBu + db, Wu + (size_t)lrow*DIMX + k0 + lch*8);
  };

  float accG[2][8][4], accU[2][8][4];
  #pragma unroll
  for (int i=0;i<2;i++)
    #pragma unroll
    for (int j=0;j<8;j++)
      #pragma unroll
      for (int k=0;k<4;k++){ accG[i][j][k]=0.f; accU[i][j][k]=0.f; }

  load_stage(0, 0); cpcommit();
  load_stage(1, 32); cpcommit();

  const int KT = DIMX/32;  // 32
  for (int kt=0; kt<KT; ++kt){
    cpwait<1>();
    __syncthreads();
    int ld = kt + 2;
    if (ld < KT) load_stage(ld%3, ld*32);
    cpcommit();
    const int buf = kt % 3;
    const uint32_t baseA = sA  + (uint32_t)buf*256*32*2;
    const uint32_t baseG = sBg + (uint32_t)buf*64*32*2;
    const uint32_t baseU = sBu + (uint32_t)buf*64*32*2;
    #pragma unroll
    for (int ks=0; ks<2; ++ks){
      uint32_t a[2][4];
      #pragma unroll
      for (int mt=0; mt<2; ++mt){
        int r  = wm*32 + mt*16 + (lane&15);
        int ch = ks*2 + (lane>>4);
        ldm4(a[mt][0],a[mt][1],a[mt][2],a[mt][3], baseA + (uint32_t)swz(r,ch)*2);
      }
      uint32_t bg[4][4], bu[4][4];
      #pragma unroll
      for (int np=0; np<4; ++np){
        int r  = np*16 + (lane&7) + ((lane>>4)<<3);
        int ch = ks*2 + ((lane>>3)&1);
        uint32_t off = (uint32_t)swz(r,ch)*2;
        ldm4(bg[np][0],bg[np][1],bg[np][2],bg[np][3], baseG + off);
        ldm4(bu[np][0],bu[np][1],bu[np][2],bu[np][3], baseU + off);
      }
      #pragma unroll
      for (int mt=0; mt<2; ++mt){
        #pragma unroll
        for (int nt=0; nt<8; ++nt){
          int np = nt>>1, p = (nt&1)*2;
          mma16816(accG[mt][nt][0],accG[mt][nt][1],accG[mt][nt][2],accG[mt][nt][3],
                   a[mt][0],a[mt][1],a[mt][2],a[mt][3], bg[np][p], bg[np][p+1]);
          mma16816(accU[mt][nt][0],accU[mt][nt][1],accU[mt][nt][2],accU[mt][nt][3],
                   a[mt][0],a[mt][1],a[mt][2],a[mt][3], bu[np][p], bu[np][p+1]);
        }
      }
    }
    __syncthreads();
  }

  // epilogue: silu(g)*u -> fp16 hidden scratch (padded rows harmless)
  const int r0 = lane>>2, c0 = (lane&3)*2;
  #pragma unroll
  for (int mt=0; mt<2; ++mt){
    #pragma unroll
    for (int hh=0; hh<2; ++hh){
      int slot = rowBase + wm*32 + mt*16 + r0 + hh*8;
      __half2* hrow = reinterpret_cast<__half2*>(g_h16 + ((size_t)e*CAP + slot)*HIDX);
      #pragma unroll
      for (int nt=0; nt<8; ++nt){
        float gv0 = accG[mt][nt][hh*2+0], gv1 = accG[mt][nt][hh*2+1];
        float uv0 = accU[mt][nt][hh*2+0], uv1 = accU[mt][nt][hh*2+1];
        float h0 = gv0 / (1.f + __expf(-gv0)) * uv0;
        float h1 = gv1 / (1.f + __expf(-gv1)) * uv1;
        int gc = nBase + nt*8 + c0;
        hrow[gc>>1] = __floats2half2_rn(h0, h1);
      }
    }
  }
}

// =============== GEMM 2: y[e][slot] = w * (hidden Dᵀ) =========================
// BM=256, BN=128, BK=32, 256 thr (warps 4m x 2n), 3-stage pipeline, dense stores.
__global__ __launch_bounds__(256,1) void gemm_down(){
  extern __shared__ __half sm[];
  const int e = blockIdx.z;
  const int cntE = g_cnt[e];
  const int rowBase = blockIdx.x * 256;
  if (rowBase >= cntE) return;
  const int nBase = blockIdx.y * 128;   // over DIM

  const int tid  = threadIdx.x;
  const int lane = tid & 31;
  const int warp = tid >> 5;
  const int wm   = warp >> 1;   // 0..3, 64 rows each
  const int wn   = warp & 1;    // 0..1, 64 cols each

  const __half* __restrict__ Ab = g_h16 + ((size_t)e*CAP + rowBase)*HIDX;
  const __half* __restrict__ Wd = g_wd + (size_t)e*HD + (size_t)nBase*HIDX;

  const int lrow = tid >> 2;    // 0..63
  const int lch  = tid & 3;

  const uint32_t sA = sptr(sm);                    // [3][256*32]
  const uint32_t sB = sA + (uint32_t)3*256*32*2;   // [3][128*32]

  auto load_stage = [&](int buf, int k0){
    #pragma unroll
    for (int i=0;i<4;i++)
      cpasync16(sA + (uint32_t)(buf*256*32 + swz(lrow+i*64, lch))*2,
                Ab + (size_t)(lrow+i*64)*HIDX + k0 + lch*8);
    #pragma unroll
    for (int i=0;i<2;i++)
      cpasync16(sB + (uint32_t)(buf*128*32 + swz(lrow+i*64, lch))*2,
                Wd + (size_t)(lrow+i*64)*HIDX + k0 + lch*8);
  };

  float acc[4][8][4];
  #pragma unroll
  for (int i=0;i<4;i++)
    #pragma unroll
    for (int j=0;j<8;j++)
      #pragma unroll
      for (int k=0;k<4;k++) acc[i][j][k]=0.f;

  load_stage(0, 0); cpcommit();
  load_stage(1, 32); cpcommit();

  const int KT = HIDX/32;   // 88
  for (int kt=0; kt<KT; ++kt){
    cpwait<1>();
    __syncthreads();
    int ld = kt + 2;
    if (ld < KT) load_stage(ld%3, ld*32);
    cpcommit();
    const int buf = kt % 3;
    const uint32_t baseA = sA + (uint32_t)buf*256*32*2;
    const uint32_t baseB = sB + (uint32_t)buf*128*32*2;
    #pragma unroll
    for (int ks=0; ks<2; ++ks){
      uint32_t a[4][4];
      #pragma unroll
      for (int mt=0; mt<4; ++mt){
        int r  = wm*64 + mt*16 + (lane&15);
        int ch = ks*2 + (lane>>4);
        ldm4(a[mt][0],a[mt][1],a[mt][2],a[mt][3], baseA + (uint32_t)swz(r,ch)*2);
      }
      uint32_t b[4][4];
      #pragma unroll
      for (int np=0; np<4; ++np){
        int r  = wn*64 + np*16 + (lane&7) + ((lane>>4)<<3);
        int ch = ks*2 + ((lane>>3)&1);
        ldm4(b[np][0],b[np][1],b[np][2],b[np][3], baseB + (uint32_t)swz(r,ch)*2);
      }
      #pragma unroll
      for (int mt=0; mt<4; ++mt){
        #pragma unroll
        for (int nt=0; nt<8; ++nt){
          int np = nt>>1, p = (nt&1)*2;
          mma16816(acc[mt][nt][0],acc[mt][nt][1],acc[mt][nt][2],acc[mt][nt][3],
                   a[mt][0],a[mt][1],a[mt][2],a[mt][3], b[np][p], b[np][p+1]);
        }
      }
    }
    __syncthreads();
  }

  // epilogue: scale by routing weight, dense store into g_y (no atomics)
  const int r0 = lane>>2, c0 = (lane&3)*2;
  #pragma unroll
  for (int mt=0; mt<4; ++mt){
    #pragma unroll
    for (int hh=0; hh<2; ++hh){
      int slot = rowBase + wm*64 + mt*16 + r0 + hh*8;
      float w = g_twf[e*CAP+slot];
      float* yrow = g_y + ((size_t)e*CAP + slot)*DIMX;
      #pragma unroll
      for (int nt=0; nt<8; ++nt){
        int gc = nBase + wn*64 + nt*8 + c0;
        float2 v = make_float2(acc[mt][nt][hh*2+0]*w, acc[mt][nt][hh*2+1]*w);
        *reinterpret_cast<float2*>(yrow + gc) = v;
      }
    }
  }
}

// ---------------- gather: out[t] = y[pos0] + y[pos1] + y[shared] --------------
__global__ void gather_k(float4* __restrict__ out){
  int i = blockIdx.x*blockDim.x + threadIdx.x;   // TTOK*256 threads
  int t = i >> 8;
  int c = i & 255;
  const float4* Y = reinterpret_cast<const float4*>(g_y);
  float4 a = Y[(size_t)g_pos[2*t]  *256 + c];
  float4 b = Y[(size_t)g_pos[2*t+1]*256 + c];
  float4 s = Y[((size_t)NE*CAP + t)*256 + c];
  out[i] = make_float4(a.x+b.x+s.x, a.y+b.y+s.y, a.z+b.z+s.z, a.w+b.w+s.w);
}

// ---------------- launch ------------------------------------------------------
extern "C" void kernel_launch(void* const* d_in, const int* in_sizes, int n_in,
                              void* d_out, int out_size){
  const float* x  = (const float*)d_in[0];
  const float* rw = (const float*)d_in[1];
  const float* eb = (const float*)d_in[2];
  const float* gw = (const float*)d_in[3];
  const float* uw = (const float*)d_in[4];
  const float* dw = (const float*)d_in[5];
  const float* sg = (const float*)d_in[6];
  const float* su = (const float*)d_in[7];
  const float* sd = (const float*)d_in[8];
  float* out = (float*)d_out;
  (void)in_sizes; (void)n_in; (void)out_size;

  static bool attr_done = false;
  const int smemGU = (3*256*32 + 3*64*32 + 3*64*32) * 2;   // 73728
  const int smemDN = (3*256*32 + 3*128*32) * 2;            // 73728
  if (!attr_done){
    cudaFuncSetAttribute(gemm_gateup, cudaFuncAttributeMaxDynamicSharedMemorySize, smemGU);
    cudaFuncSetAttribute(gemm_down,   cudaFuncAttributeMaxDynamicSharedMemorySize, smemDN);
    attr_done = true;
  }

  auto cvt = [&](const float* s, int seg, long n){
    int n4 = (int)(n/4);
    cvt_seg<<<(n4+255)/256, 256>>>(s, seg, n4);
  };
  cvt(x,  0, (long)TTOK*DIMX);
  cvt(gw, 1, (long)NE*HD);
  cvt(uw, 2, (long)NE*HD);
  cvt(dw, 3, (long)NE*HD);
  cvt(sg, 4, (long)HD);
  cvt(su, 5, (long)HD);
  cvt(sd, 6, (long)HD);

  init_k<<<TTOK/256, 256>>>();
  router_k<<<TTOK/8, 256>>>(x, rw, eb);

  gemm_gateup<<<dim3(CAP/256, HIDX/64, NEX), 256, smemGU>>>();
  gemm_down  <<<dim3(CAP/256, DIMX/128, NEX), 256, smemDN>>>();
  gather_k<<<TTOK*256/256, 256>>>((float4*)out);
}

// round 4
// speedup vs baseline: 1.6031x; 1.4216x over previous
#include <cuda_runtime.h>
#include <cuda_fp16.h>
#include <cuda.h>
#include <cstdint>

#define TTOK 8192
#define DIMX 1024
#define HIDX 2816
#define NE 8
#define NEX 9          // 8 routed experts + shared expert as expert 8
#define CAP 8192
#define HD (HIDX*DIMX)

#define NSTG 4
#define STAGE_BYTES 49152              // A 256x128B (32KB) + B 128x128B (16KB)
#define SMEM_DYN (NSTG*STAGE_BYTES + 1024)

// ---------------- scratch (static device globals; no allocations) -------------
__device__ __align__(1024) __half g_xs[(size_t)NEX*CAP*DIMX];   // slot-ordered x
__device__ __align__(1024) __half g_wg[(size_t)NEX*HD];
__device__ __align__(1024) __half g_wu[(size_t)NEX*HD];
__device__ __align__(1024) __half g_wd[(size_t)NEX*HD];
__device__ __align__(1024) __half g_h16[(size_t)NEX*CAP*HIDX];  // hidden acts
__device__ __align__(1024) float  g_y[(size_t)NEX*CAP*DIMX];
__device__ int    g_cnt[NEX];
__device__ float  g_twf[NEX*CAP];
__device__ int    g_pos[2*TTOK];
// tensormaps: [0]=gu_A(g_xs) [1]=gu_G [2]=gu_U [3]=dn_A(g_h16) [4]=dn_B(g_wd)
__device__ __align__(64) CUtensorMap g_tmap[5];

// ---------------- device helpers ----------------------------------------------
__device__ __forceinline__ uint32_t sptr(const void* p){
  return (uint32_t)__cvta_generic_to_shared(p);
}
__device__ __forceinline__ void mbar_init(uint32_t a, uint32_t n){
  asm volatile("mbarrier.init.shared.b64 [%0], %1;" :: "r"(a), "r"(n) : "memory");
}
__device__ __forceinline__ void mbar_arrive(uint32_t a){
  asm volatile("mbarrier.arrive.shared.b64 _, [%0];" :: "r"(a) : "memory");
}
__device__ __forceinline__ void mbar_expect(uint32_t a, uint32_t tx){
  asm volatile("mbarrier.arrive.expect_tx.shared.b64 _, [%0], %1;" :: "r"(a), "r"(tx) : "memory");
}
__device__ __forceinline__ void mbar_wait(uint32_t a, uint32_t parity){
  uint32_t done;
  asm volatile(
    "{\n\t.reg .pred p;\n\t"
    "mbarrier.try_wait.parity.acquire.cta.shared::cta.b64 p, [%1], %2;\n\t"
    "selp.b32 %0, 1, 0, p;\n\t}"
    : "=r"(done) : "r"(a), "r"(parity) : "memory");
  if (!done){
    asm volatile(
      "{\n\t.reg .pred P1;\n\t"
      "WL_%=:\n\t"
      "mbarrier.try_wait.parity.acquire.cta.shared::cta.b64 P1, [%0], %1, 0x989680;\n\t"
      "@P1 bra.uni WD_%=;\n\t"
      "bra.uni WL_%=;\n\t"
      "WD_%=:\n\t}"
      :: "r"(a), "r"(parity) : "memory");
  }
}
__device__ __forceinline__ void tma2d(uint32_t dst, const CUtensorMap* tm,
                                      int cx, int cy, uint32_t bar){
  asm volatile(
    "cp.async.bulk.tensor.2d.shared::cta.global.tile.mbarrier::complete_tx::bytes "
    "[%0], [%1, {%2, %3}], [%4];"
    :: "r"(dst), "l"(tm), "r"(cx), "r"(cy), "r"(bar) : "memory");
}
__device__ __forceinline__ void ldm4(uint32_t &r0,uint32_t &r1,uint32_t &r2,uint32_t &r3,uint32_t addr){
  asm volatile("ldmatrix.sync.aligned.m8n8.x4.shared.b16 {%0,%1,%2,%3}, [%4];\n"
    : "=r"(r0),"=r"(r1),"=r"(r2),"=r"(r3) : "r"(addr));
}
__device__ __forceinline__ void mma16816(float&d0,float&d1,float&d2,float&d3,
   uint32_t a0,uint32_t a1,uint32_t a2,uint32_t a3,uint32_t b0,uint32_t b1){
  asm volatile("mma.sync.aligned.m16n8k16.row.col.f32.f16.f16.f32 "
    "{%0,%1,%2,%3},{%4,%5,%6,%7},{%8,%9},{%0,%1,%2,%3};\n"
    : "+f"(d0),"+f"(d1),"+f"(d2),"+f"(d3)
    : "r"(a0),"r"(a1),"r"(a2),"r"(a3),"r"(b0),"r"(b1));
}
// SW128 swizzled smem byte offset for row r (128B rows), 16B chunk c
__device__ __forceinline__ uint32_t swoff(int r, int c){
  return (uint32_t)(r*128 + ((c ^ (r&7))<<4));
}

// ---------------- conversion fp32 -> fp16 (weights only) -----------------------
__global__ void cvt_seg(const float* __restrict__ src, int seg, int n4){
  int i = blockIdx.x*blockDim.x + threadIdx.x;
  if (i >= n4) return;
  __half* dst;
  switch(seg){
    case 1: dst = g_wg;  break;
    case 2: dst = g_wu;  break;
    case 3: dst = g_wd;  break;
    case 4: dst = g_wg + (size_t)NE*HD; break;
    case 5: dst = g_wu + (size_t)NE*HD; break;
    default: dst = g_wd + (size_t)NE*HD; break;
  }
  float4 v = reinterpret_cast<const float4*>(src)[i];
  __half2* d2 = reinterpret_cast<__half2*>(dst) + 2*(size_t)i;
  d2[0] = __floats2half2_rn(v.x, v.y);
  d2[1] = __floats2half2_rn(v.z, v.w);
}

// ---------------- init + router ------------------------------------------------
__global__ void init_k(){
  int i = blockIdx.x*blockDim.x + threadIdx.x;
  if (i < NE)  g_cnt[i] = 0;
  if (i == NE) g_cnt[NE] = TTOK;
  if (i < TTOK) g_twf[NE*CAP+i] = 1.0f;
}

__global__ void router_k(const float* __restrict__ x, const float* __restrict__ rw,
                         const float* __restrict__ eb){
  int t = blockIdx.x*8 + (threadIdx.x>>5);
  int lane = threadIdx.x & 31;
  if (t >= TTOK) return;
  const float* xr = x + (size_t)t*DIMX;
  float acc[NE];
  #pragma unroll
  for (int e=0;e<NE;e++) acc[e]=0.f;
  for (int k = lane; k < DIMX; k += 32){
    float xv = xr[k];
    #pragma unroll
    for (int e=0;e<NE;e++) acc[e] = fmaf(xv, rw[e*DIMX+k], acc[e]);
  }
  #pragma unroll
  for (int e=0;e<NE;e++){
    #pragma unroll
    for (int o=16;o>0;o>>=1) acc[e] += __shfl_xor_sync(0xffffffffu, acc[e], o);
  }
  if (lane==0){
    float s[NE];
    #pragma unroll
    for (int e=0;e<NE;e++){
      float l = acc[e] + eb[e];
      s[e] = 1.f / (1.f + __expf(-l));
    }
    int i0=0;
    #pragma unroll
    for (int e=1;e<NE;e++) if (s[e] > s[i0]) i0=e;
    int i1 = (i0==0)?1:0;
    #pragma unroll
    for (int e=0;e<NE;e++) if (e!=i0 && s[e] > s[i1]) i1=e;
    float inv = 1.f / (s[i0]+s[i1]+1e-6f);
    int p0 = atomicAdd(&g_cnt[i0], 1);
    g_twf[i0*CAP+p0]=s[i0]*inv; g_pos[2*t]   = i0*CAP+p0;
    int p1 = atomicAdd(&g_cnt[i1], 1);
    g_twf[i1*CAP+p1]=s[i1]*inv; g_pos[2*t+1] = i1*CAP+p1;
  }
}

// ---------------- scatter x (fp32 -> fp16) into slot order --------------------
__global__ void scatter_x(const float* __restrict__ x){
  int t = blockIdx.x;          // token
  int c = threadIdx.x;         // 128 threads, 8 halves each
  const float4* xr = reinterpret_cast<const float4*>(x + (size_t)t*DIMX) + 2*c;
  float4 v0 = xr[0], v1 = xr[1];
  __half2 h[4] = { __floats2half2_rn(v0.x,v0.y), __floats2half2_rn(v0.z,v0.w),
                   __floats2half2_rn(v1.x,v1.y), __floats2half2_rn(v1.z,v1.w) };
  uint4 pack = *reinterpret_cast<uint4*>(h);
  int p0 = g_pos[2*t], p1 = g_pos[2*t+1], ps = NE*CAP + t;
  uint4* base = reinterpret_cast<uint4*>(g_xs);
  base[(size_t)p0*128 + c] = pack;
  base[(size_t)p1*128 + c] = pack;
  base[(size_t)ps*128 + c] = pack;
}

// =============== GEMM 1 (TMA): hidden = silu(X Gᵀ) * (X Uᵀ) ===================
// BM=256, B tile = 64 gate rows + 64 up rows, BK=64, 8 m-warps, 4-stage TMA.
__global__ __launch_bounds__(256,1) void gemm_gateup(){
  extern __shared__ char smraw[];
  __shared__ __align__(8) uint64_t full[NSTG], empty[NSTG];
  const int e = blockIdx.z;
  const int cntE = g_cnt[e];
  const int rowBase = blockIdx.x*256;
  if (rowBase >= cntE) return;
  const int nBase = blockIdx.y*64;          // hidden dims this block
  const int tid = threadIdx.x, lane = tid&31, wid = tid>>5;
  const uint32_t base = (sptr(smraw)+1023u) & ~1023u;
  const int KT = DIMX/64;                   // 16

  if (tid==0){
    #pragma unroll
    for (int s=0;s<NSTG;s++){ mbar_init(sptr(&full[s]),1); mbar_init(sptr(&empty[s]),256); }
    asm volatile("fence.mbarrier_init.release.cluster;" ::: "memory");
  }
  __syncthreads();

  auto issue = [&](int ld){
    uint32_t sa = base + (ld%NSTG)*STAGE_BYTES;
    uint32_t bar = sptr(&full[ld%NSTG]);
    mbar_expect(bar, STAGE_BYTES);
    tma2d(sa,          &g_tmap[0], ld*64, e*CAP + rowBase, bar);
    tma2d(sa+32768,    &g_tmap[1], ld*64, e*HIDX + nBase,  bar);
    tma2d(sa+32768+8192,&g_tmap[2], ld*64, e*HIDX + nBase, bar);
  };
  if (tid==0){ issue(0); issue(1); issue(2); }

  float acc[2][16][4];
  #pragma unroll
  for (int i=0;i<2;i++)
    #pragma unroll
    for (int j=0;j<16;j++)
      #pragma unroll
      for (int k=0;k<4;k++) acc[i][j][k]=0.f;

  for (int kt=0; kt<KT; ++kt){
    const int s = kt%NSTG;
    if (tid==0){
      int ld = kt + (NSTG-1);
      if (ld < KT){
        if (ld >= NSTG) mbar_wait(sptr(&empty[ld%NSTG]), ((ld/NSTG)-1)&1);
        issue(ld);
      }
    }
    mbar_wait(sptr(&full[s]), (kt/NSTG)&1);
    const uint32_t bA = base + s*STAGE_BYTES;
    const uint32_t bB = bA + 32768;
    #pragma unroll
    for (int ks=0; ks<4; ++ks){
      uint32_t a[2][4];
      #pragma unroll
      for (int mt=0; mt<2; ++mt){
        int r = wid*32 + mt*16 + (lane&15);
        ldm4(a[mt][0],a[mt][1],a[mt][2],a[mt][3], bA + swoff(r, ks*2 + (lane>>4)));
      }
      uint32_t b[8][4];
      #pragma unroll
      for (int np=0; np<8; ++np){
        int r = np*16 + (lane&7) + ((lane>>4)<<3);
        ldm4(b[np][0],b[np][1],b[np][2],b[np][3], bB + swoff(r, ks*2 + ((lane>>3)&1)));
      }
      #pragma unroll
      for (int mt=0; mt<2; ++mt){
        #pragma unroll
        for (int nt=0; nt<16; ++nt){
          int np = nt>>1, p = (nt&1)*2;
          mma16816(acc[mt][nt][0],acc[mt][nt][1],acc[mt][nt][2],acc[mt][nt][3],
                   a[mt][0],a[mt][1],a[mt][2],a[mt][3], b[np][p], b[np][p+1]);
        }
      }
    }
    mbar_arrive(sptr(&empty[s]));
  }

  // epilogue: silu(gate)*up -> fp16 hidden (nt 0..7 = gate, 8..15 = up)
  const int r0 = lane>>2, c0 = (lane&3)*2;
  #pragma unroll
  for (int mt=0; mt<2; ++mt){
    #pragma unroll
    for (int hh=0; hh<2; ++hh){
      int slot = rowBase + wid*32 + mt*16 + r0 + hh*8;
      __half* hrow = g_h16 + ((size_t)e*CAP + slot)*HIDX + nBase;
      #pragma unroll
      for (int nt=0; nt<8; ++nt){
        float g0 = acc[mt][nt][hh*2+0],   g1 = acc[mt][nt][hh*2+1];
        float u0 = acc[mt][nt+8][hh*2+0], u1 = acc[mt][nt+8][hh*2+1];
        float h0 = g0/(1.f+__expf(-g0))*u0;
        float h1 = g1/(1.f+__expf(-g1))*u1;
        *reinterpret_cast<__half2*>(hrow + nt*8 + c0) = __floats2half2_rn(h0,h1);
      }
    }
  }
}

// =============== GEMM 2 (TMA): y[e][slot] = w * (hidden Dᵀ) ====================
// BM=256, BN=128, BK=64, 8 m-warps, 4-stage TMA, dense g_y stores.
__global__ __launch_bounds__(256,1) void gemm_down(){
  extern __shared__ char smraw[];
  __shared__ __align__(8) uint64_t full[NSTG], empty[NSTG];
  const int e = blockIdx.z;
  const int cntE = g_cnt[e];
  const int rowBase = blockIdx.x*256;
  if (rowBase >= cntE) return;
  const int nBase = blockIdx.y*128;         // DIM cols this block
  const int tid = threadIdx.x, lane = tid&31, wid = tid>>5;
  const uint32_t base = (sptr(smraw)+1023u) & ~1023u;
  const int KT = HIDX/64;                   // 44

  if (tid==0){
    #pragma unroll
    for (int s=0;s<NSTG;s++){ mbar_init(sptr(&full[s]),1); mbar_init(sptr(&empty[s]),256); }
    asm volatile("fence.mbarrier_init.release.cluster;" ::: "memory");
  }
  __syncthreads();

  auto issue = [&](int ld){
    uint32_t sa = base + (ld%NSTG)*STAGE_BYTES;
    uint32_t bar = sptr(&full[ld%NSTG]);
    mbar_expect(bar, STAGE_BYTES);
    tma2d(sa,       &g_tmap[3], ld*64, e*CAP + rowBase, bar);
    tma2d(sa+32768, &g_tmap[4], ld*64, e*DIMX + nBase,  bar);
  };
  if (tid==0){ issue(0); issue(1); issue(2); }

  float acc[2][16][4];
  #pragma unroll
  for (int i=0;i<2;i++)
    #pragma unroll
    for (int j=0;j<16;j++)
      #pragma unroll
      for (int k=0;k<4;k++) acc[i][j][k]=0.f;

  for (int kt=0; kt<KT; ++kt){
    const int s = kt%NSTG;
    if (tid==0){
      int ld = kt + (NSTG-1);
      if (ld < KT){
        if (ld >= NSTG) mbar_wait(sptr(&empty[ld%NSTG]), ((ld/NSTG)-1)&1);
        issue(ld);
      }
    }
    mbar_wait(sptr(&full[s]), (kt/NSTG)&1);
    const uint32_t bA = base + s*STAGE_BYTES;
    const uint32_t bB = bA + 32768;
    #pragma unroll
    for (int ks=0; ks<4; ++ks){
      uint32_t a[2][4];
      #pragma unroll
      for (int mt=0; mt<2; ++mt){
        int r = wid*32 + mt*16 + (lane&15);
        ldm4(a[mt][0],a[mt][1],a[mt][2],a[mt][3], bA + swoff(r, ks*2 + (lane>>4)));
      }
      uint32_t b[8][4];
      #pragma unroll
      for (int np=0; np<8; ++np){
        int r = np*16 + (lane&7) + ((lane>>4)<<3);
        ldm4(b[np][0],b[np][1],b[np][2],b[np][3], bB + swoff(r, ks*2 + ((lane>>3)&1)));
      }
      #pragma unroll
      for (int mt=0; mt<2; ++mt){
        #pragma unroll
        for (int nt=0; nt<16; ++nt){
          int np = nt>>1, p = (nt&1)*2;
          mma16816(acc[mt][nt][0],acc[mt][nt][1],acc[mt][nt][2],acc[mt][nt][3],
                   a[mt][0],a[mt][1],a[mt][2],a[mt][3], b[np][p], b[np][p+1]);
        }
      }
    }
    mbar_arrive(sptr(&empty[s]));
  }

  // epilogue: scale by routing weight, dense store into g_y
  const int r0 = lane>>2, c0 = (lane&3)*2;
  #pragma unroll
  for (int mt=0; mt<2; ++mt){
    #pragma unroll
    for (int hh=0; hh<2; ++hh){
      int slot = rowBase + wid*32 + mt*16 + r0 + hh*8;
      float w = g_twf[e*CAP+slot];
      float* yrow = g_y + ((size_t)e*CAP + slot)*DIMX + nBase;
      #pragma unroll
      for (int nt=0; nt<16; ++nt){
        float2 v = make_float2(acc[mt][nt][hh*2+0]*w, acc[mt][nt][hh*2+1]*w);
        *reinterpret_cast<float2*>(yrow + nt*8 + c0) = v;
      }
    }
  }
}

// ---------------- gather: out[t] = y[pos0] + y[pos1] + y[shared] --------------
__global__ void gather_k(float4* __restrict__ out){
  int i = blockIdx.x*blockDim.x + threadIdx.x;
  int t = i >> 8;
  int c = i & 255;
  const float4* Y = reinterpret_cast<const float4*>(g_y);
  float4 a = Y[(size_t)g_pos[2*t]  *256 + c];
  float4 b = Y[(size_t)g_pos[2*t+1]*256 + c];
  float4 s = Y[((size_t)NE*CAP + t)*256 + c];
  out[i] = make_float4(a.x+b.x+s.x, a.y+b.y+s.y, a.z+b.z+s.z, a.w+b.w+s.w);
}

// ---------------- host-side tensormap setup -----------------------------------
typedef CUresult (*EncodeFn)(CUtensorMap*, CUtensorMapDataType, cuuint32_t, void*,
                             const cuuint64_t*, const cuuint64_t*, const cuuint32_t*,
                             const cuuint32_t*, CUtensorMapInterleave, CUtensorMapSwizzle,
                             CUtensorMapL2promotion, CUtensorMapFloatOOBfill);

static void encode2d(EncodeFn fn, CUtensorMap* tm, void* ptr,
                     uint64_t cols, uint64_t rows, uint32_t boxc, uint32_t boxr){
  cuuint64_t dims[2]    = { cols, rows };
  cuuint64_t strides[1] = { cols * 2 };          // fp16 row pitch in bytes
  cuuint32_t box[2]     = { boxc, boxr };
  cuuint32_t estr[2]    = { 1, 1 };
  fn(tm, CU_TENSOR_MAP_DATA_TYPE_FLOAT16, 2, ptr, dims, strides, box, estr,
     CU_TENSOR_MAP_INTERLEAVE_NONE, CU_TENSOR_MAP_SWIZZLE_128B,
     CU_TENSOR_MAP_L2_PROMOTION_L2_128B, CU_TENSOR_MAP_FLOAT_OOB_FILL_NONE);
}

extern "C" void kernel_launch(void* const* d_in, const int* in_sizes, int n_in,
                              void* d_out, int out_size){
  const float* x  = (const float*)d_in[0];
  const float* rw = (const float*)d_in[1];
  const float* eb = (const float*)d_in[2];
  const float* gw = (const float*)d_in[3];
  const float* uw = (const float*)d_in[4];
  const float* dw = (const float*)d_in[5];
  const float* sg = (const float*)d_in[6];
  const float* su = (const float*)d_in[7];
  const float* sd = (const float*)d_in[8];
  float* out = (float*)d_out;
  (void)in_sizes; (void)n_in; (void)out_size;

  static bool setup_done = false;
  if (!setup_done){
    cudaFuncSetAttribute(gemm_gateup, cudaFuncAttributeMaxDynamicSharedMemorySize, SMEM_DYN);
    cudaFuncSetAttribute(gemm_down,   cudaFuncAttributeMaxDynamicSharedMemorySize, SMEM_DYN);
    void* fn = nullptr;
    cudaDriverEntryPointQueryResult qr;
    cudaGetDriverEntryPoint("cuTensorMapEncodeTiled", &fn, cudaEnableDefault, &qr);
    EncodeFn enc = (EncodeFn)fn;
    void *p_xs, *p_wg, *p_wu, *p_wd, *p_h;
    cudaGetSymbolAddress(&p_xs, g_xs);
    cudaGetSymbolAddress(&p_wg, g_wg);
    cudaGetSymbolAddress(&p_wu, g_wu);
    cudaGetSymbolAddress(&p_wd, g_wd);
    cudaGetSymbolAddress(&p_h,  g_h16);
    static CUtensorMap h_tm[5];
    encode2d(enc, &h_tm[0], p_xs, DIMX, (uint64_t)NEX*CAP,  64, 256);  // gu A
    encode2d(enc, &h_tm[1], p_wg, DIMX, (uint64_t)NEX*HIDX, 64, 64);   // gu gate
    encode2d(enc, &h_tm[2], p_wu, DIMX, (uint64_t)NEX*HIDX, 64, 64);   // gu up
    encode2d(enc, &h_tm[3], p_h,  HIDX, (uint64_t)NEX*CAP,  64, 256);  // dn A
    encode2d(enc, &h_tm[4], p_wd, HIDX, (uint64_t)NEX*DIMX, 64, 128);  // dn B
    cudaMemcpyToSymbolAsync(g_tmap, h_tm, 5*sizeof(CUtensorMap), 0,
                            cudaMemcpyHostToDevice, 0);
    setup_done = true;
  }

  auto cvt = [&](const float* s, int seg, long n){
    int n4 = (int)(n/4);
    cvt_seg<<<(n4+255)/256, 256>>>(s, seg, n4);
  };
  cvt(gw, 1, (long)NE*HD);
  cvt(uw, 2, (long)NE*HD);
  cvt(dw, 3, (long)NE*HD);
  cvt(sg, 4, (long)HD);
  cvt(su, 5, (long)HD);
  cvt(sd, 6, (long)HD);

  init_k<<<TTOK/256, 256>>>();
  router_k<<<TTOK/8, 256>>>(x, rw, eb);
  scatter_x<<<TTOK, 128>>>(x);

  gemm_gateup<<<dim3(CAP/256, HIDX/64, NEX), 256, SMEM_DYN>>>();
  gemm_down  <<<dim3(CAP/256, DIMX/128, NEX), 256, SMEM_DYN>>>();
  gather_k<<<TTOK*1024/4/256, 256>>>((float4*)out);
}

// round 6
// speedup vs baseline: 1.6183x; 1.0095x over previous
#include <cuda_runtime.h>
#include <cuda_fp16.h>
#include <cuda.h>
#include <cstdint>

#define TTOK 8192
#define DIMX 1024
#define HIDX 2816
#define NE 8
#define NEX 9          // 8 routed experts + shared expert as expert 8
#define CAP 8192
#define HD (HIDX*DIMX)

#define NSTG 4
#define STAGE_BYTES 49152              // A 256x128B (32KB) + B 128x128B (16KB)
#define SMEM_DYN (NSTG*STAGE_BYTES + 1024)

// ---------------- scratch (static device globals; no allocations) -------------
__device__ __align__(1024) __half g_xs[(size_t)NEX*CAP*DIMX];   // slot-ordered x
__device__ __align__(1024) __half g_wg[(size_t)NEX*HD];
__device__ __align__(1024) __half g_wu[(size_t)NEX*HD];
__device__ __align__(1024) __half g_wd[(size_t)NEX*HD];
__device__ __align__(1024) __half g_h16[(size_t)NEX*CAP*HIDX];  // hidden acts
__device__ __align__(1024) float  g_y[(size_t)NEX*CAP*DIMX];
__device__ int    g_cnt[NEX];
__device__ float  g_twf[NEX*CAP];
__device__ int    g_pos[2*TTOK];
// tensormaps: [0]=gu_A(g_xs) [1]=gu_G [2]=gu_U [3]=dn_A(g_h16) [4]=dn_B(g_wd)
__device__ __align__(64) CUtensorMap g_tmap[5];

// ---------------- device helpers ----------------------------------------------
__device__ __forceinline__ uint32_t sptr(const void* p){
  return (uint32_t)__cvta_generic_to_shared(p);
}
__device__ __forceinline__ void mbar_init(uint32_t a, uint32_t n){
  asm volatile("mbarrier.init.shared.b64 [%0], %1;" :: "r"(a), "r"(n) : "memory");
}
__device__ __forceinline__ void mbar_arrive(uint32_t a){
  asm volatile("mbarrier.arrive.shared.b64 _, [%0];" :: "r"(a) : "memory");
}
__device__ __forceinline__ void mbar_expect(uint32_t a, uint32_t tx){
  asm volatile("mbarrier.arrive.expect_tx.shared.b64 _, [%0], %1;" :: "r"(a), "r"(tx) : "memory");
}
__device__ __forceinline__ void mbar_wait(uint32_t a, uint32_t parity){
  uint32_t done;
  asm volatile(
    "{\n\t.reg .pred p;\n\t"
    "mbarrier.try_wait.parity.acquire.cta.shared::cta.b64 p, [%1], %2;\n\t"
    "selp.b32 %0, 1, 0, p;\n\t}"
    : "=r"(done) : "r"(a), "r"(parity) : "memory");
  if (!done){
    asm volatile(
      "{\n\t.reg .pred P1;\n\t"
      "WL_%=:\n\t"
      "mbarrier.try_wait.parity.acquire.cta.shared::cta.b64 P1, [%0], %1, 0x989680;\n\t"
      "@P1 bra.uni WD_%=;\n\t"
      "bra.uni WL_%=;\n\t"
      "WD_%=:\n\t}"
      :: "r"(a), "r"(parity) : "memory");
  }
}
__device__ __forceinline__ void tma2d(uint32_t dst, const CUtensorMap* tm,
                                      int cx, int cy, uint32_t bar){
  asm volatile(
    "cp.async.bulk.tensor.2d.shared::cta.global.tile.mbarrier::complete_tx::bytes "
    "[%0], [%1, {%2, %3}], [%4];"
    :: "r"(dst), "l"(tm), "r"(cx), "r"(cy), "r"(bar) : "memory");
}
__device__ __forceinline__ void ldm4(uint32_t &r0,uint32_t &r1,uint32_t &r2,uint32_t &r3,uint32_t addr){
  asm volatile("ldmatrix.sync.aligned.m8n8.x4.shared.b16 {%0,%1,%2,%3}, [%4];\n"
    : "=r"(r0),"=r"(r1),"=r"(r2),"=r"(r3) : "r"(addr));
}
__device__ __forceinline__ void mma16816(float&d0,float&d1,float&d2,float&d3,
   uint32_t a0,uint32_t a1,uint32_t a2,uint32_t a3,uint32_t b0,uint32_t b1){
  asm volatile("mma.sync.aligned.m16n8k16.row.col.f32.f16.f16.f32 "
    "{%0,%1,%2,%3},{%4,%5,%6,%7},{%8,%9},{%0,%1,%2,%3};\n"
    : "+f"(d0),"+f"(d1),"+f"(d2),"+f"(d3)
    : "r"(a0),"r"(a1),"r"(a2),"r"(a3),"r"(b0),"r"(b1));
}
// SW128 swizzled smem byte offset for row r (128B rows), 16B chunk c
__device__ __forceinline__ uint32_t swoff(int r, int c){
  return (uint32_t)(r*128 + ((c ^ (r&7))<<4));
}

// ---------------- conversions (2 launches total) -------------------------------
// NOTE: dst is the SEGMENT BASE; i is the segment-relative float4 index.
__device__ __forceinline__ void cvt4(__half* dst, const float* __restrict__ src, size_t i){
  float4 v = reinterpret_cast<const float4*>(src)[i];
  __half2* d2 = reinterpret_cast<__half2*>(dst) + 2*i;
  d2[0] = __floats2half2_rn(v.x, v.y);
  d2[1] = __floats2half2_rn(v.z, v.w);
}
// launch 0: gate (gw|sg) + up (uw|su)
__global__ void cvt_a(const float* __restrict__ gw, const float* __restrict__ uw,
                      const float* __restrict__ sg, const float* __restrict__ su){
  size_t i = (size_t)blockIdx.x*blockDim.x + threadIdx.x;   // float4 index
  const size_t Q  = (size_t)NE*HD/4;    // routed portion per tensor
  const size_t QT = (size_t)NEX*HD/4;   // full tensor
  if (i < QT){
    if (i < Q) cvt4(g_wg, gw, i);
    else       cvt4(g_wg + (size_t)NE*HD, sg, i-Q);
  } else {
    size_t j = i - QT;
    if (j < Q) cvt4(g_wu, uw, j);
    else       cvt4(g_wu + (size_t)NE*HD, su, j-Q);
  }
}
// launch 1: down (dw|sd)
__global__ void cvt_b(const float* __restrict__ dw, const float* __restrict__ sd){
  size_t i = (size_t)blockIdx.x*blockDim.x + threadIdx.x;
  const size_t Q = (size_t)NE*HD/4;
  if (i < Q) cvt4(g_wd, dw, i);
  else       cvt4(g_wd + (size_t)NE*HD, sd, i-Q);
}

// ---------------- init + router + scatter --------------------------------------
__global__ void init_k(){
  int i = blockIdx.x*blockDim.x + threadIdx.x;
  if (i < NE)  g_cnt[i] = 0;
  if (i == NE) g_cnt[NE] = TTOK;
  if (i < TTOK) g_twf[NE*CAP+i] = 1.0f;
}

__global__ void router_k(const float* __restrict__ x, const float* __restrict__ rw,
                         const float* __restrict__ eb){
  int t = blockIdx.x*8 + (threadIdx.x>>5);
  int lane = threadIdx.x & 31;
  if (t >= TTOK) return;
  const float* xr = x + (size_t)t*DIMX;
  float acc[NE];
  #pragma unroll
  for (int e=0;e<NE;e++) acc[e]=0.f;
  for (int k = lane; k < DIMX; k += 32){
    float xv = xr[k];
    #pragma unroll
    for (int e=0;e<NE;e++) acc[e] = fmaf(xv, rw[e*DIMX+k], acc[e]);
  }
  #pragma unroll
  for (int e=0;e<NE;e++){
    #pragma unroll
    for (int o=16;o>0;o>>=1) acc[e] += __shfl_xor_sync(0xffffffffu, acc[e], o);
  }
  if (lane==0){
    float s[NE];
    #pragma unroll
    for (int e=0;e<NE;e++){
      float l = acc[e] + eb[e];
      s[e] = 1.f / (1.f + __expf(-l));
    }
    int i0=0;
    #pragma unroll
    for (int e=1;e<NE;e++) if (s[e] > s[i0]) i0=e;
    int i1 = (i0==0)?1:0;
    #pragma unroll
    for (int e=0;e<NE;e++) if (e!=i0 && s[e] > s[i1]) i1=e;
    float inv = 1.f / (s[i0]+s[i1]+1e-6f);
    int p0 = atomicAdd(&g_cnt[i0], 1);
    g_twf[i0*CAP+p0]=s[i0]*inv; g_pos[2*t]   = i0*CAP+p0;
    int p1 = atomicAdd(&g_cnt[i1], 1);
    g_twf[i1*CAP+p1]=s[i1]*inv; g_pos[2*t+1] = i1*CAP+p1;
  }
}

__global__ void scatter_x(const float* __restrict__ x){
  int t = blockIdx.x;
  int c = threadIdx.x;         // 128 threads, 8 halves each
  const float4* xr = reinterpret_cast<const float4*>(x + (size_t)t*DIMX) + 2*c;
  float4 v0 = xr[0], v1 = xr[1];
  __half2 h[4] = { __floats2half2_rn(v0.x,v0.y), __floats2half2_rn(v0.z,v0.w),
                   __floats2half2_rn(v1.x,v1.y), __floats2half2_rn(v1.z,v1.w) };
  uint4 pack = *reinterpret_cast<uint4*>(h);
  int p0 = g_pos[2*t], p1 = g_pos[2*t+1], ps = NE*CAP + t;
  uint4* base = reinterpret_cast<uint4*>(g_xs);
  base[(size_t)p0*128 + c] = pack;
  base[(size_t)p1*128 + c] = pack;
  base[(size_t)ps*128 + c] = pack;
}

// =============== GEMM 1 (TMA): hidden = silu(X Gᵀ) * (X Uᵀ) ===================
// BM=256, B tile = 64 gate + 64 up rows, BK=64; warps 4m x 2n; 4-stage TMA.
__global__ __launch_bounds__(256,1) void gemm_gateup(){
  extern __shared__ char smraw[];
  __shared__ __align__(8) uint64_t full[NSTG], empty[NSTG];
  const int e = blockIdx.z;
  const int cntE = g_cnt[e];
  const int rowBase = blockIdx.x*256;
  if (rowBase >= cntE) return;
  const int nBase = blockIdx.y*64;
  const int tid = threadIdx.x, lane = tid&31, warp = tid>>5;
  const int wm = warp>>1, wn = warp&1;
  const uint32_t base = (sptr(smraw)+1023u) & ~1023u;
  const int KT = DIMX/64;

  if (tid==0){
    #pragma unroll
    for (int s=0;s<NSTG;s++){ mbar_init(sptr(&full[s]),1); mbar_init(sptr(&empty[s]),256); }
    asm volatile("fence.mbarrier_init.release.cluster;" ::: "memory");
  }
  __syncthreads();

  auto issue = [&](int ld){
    uint32_t sa = base + (ld%NSTG)*STAGE_BYTES;
    uint32_t bar = sptr(&full[ld%NSTG]);
    mbar_expect(bar, STAGE_BYTES);
    tma2d(sa,           &g_tmap[0], ld*64, e*CAP + rowBase, bar);
    tma2d(sa+32768,     &g_tmap[1], ld*64, e*HIDX + nBase,  bar);
    tma2d(sa+32768+8192,&g_tmap[2], ld*64, e*HIDX + nBase,  bar);
  };
  if (tid==0){ issue(0); issue(1); issue(2); }

  float acc[4][8][4];
  #pragma unroll
  for (int i=0;i<4;i++)
    #pragma unroll
    for (int j=0;j<8;j++)
      #pragma unroll
      for (int k=0;k<4;k++) acc[i][j][k]=0.f;

  for (int kt=0; kt<KT; ++kt){
    const int s = kt%NSTG;
    if (tid==0){
      int ld = kt + (NSTG-1);
      if (ld < KT){
        if (ld >= NSTG) mbar_wait(sptr(&empty[ld%NSTG]), ((ld/NSTG)-1)&1);
        issue(ld);
      }
    }
    mbar_wait(sptr(&full[s]), (kt/NSTG)&1);
    const uint32_t bA = base + s*STAGE_BYTES;
    const uint32_t bB = bA + 32768;
    #pragma unroll
    for (int ks=0; ks<4; ++ks){
      uint32_t a[4][4];
      #pragma unroll
      for (int mt=0; mt<4; ++mt){
        int r = wm*64 + mt*16 + (lane&15);
        ldm4(a[mt][0],a[mt][1],a[mt][2],a[mt][3], bA + swoff(r, ks*2 + (lane>>4)));
      }
      uint32_t b[4][4];   // j 0..1: gate, j 2..3: up
      #pragma unroll
      for (int j=0; j<4; ++j){
        int r = ((j>>1)<<6) + wn*32 + (j&1)*16 + (lane&7) + ((lane>>4)<<3);
        ldm4(b[j][0],b[j][1],b[j][2],b[j][3], bB + swoff(r, ks*2 + ((lane>>3)&1)));
      }
      #pragma unroll
      for (int mt=0; mt<4; ++mt){
        #pragma unroll
        for (int nt=0; nt<8; ++nt){   // nt 0..3 gate, 4..7 up
          int j = nt>>1, p = (nt&1)*2;
          mma16816(acc[mt][nt][0],acc[mt][nt][1],acc[mt][nt][2],acc[mt][nt][3],
                   a[mt][0],a[mt][1],a[mt][2],a[mt][3], b[j][p], b[j][p+1]);
        }
      }
    }
    mbar_arrive(sptr(&empty[s]));
  }

  // epilogue: silu(gate)*up -> fp16 hidden
  const int r0 = lane>>2, c0 = (lane&3)*2;
  #pragma unroll
  for (int mt=0; mt<4; ++mt){
    #pragma unroll
    for (int hh=0; hh<2; ++hh){
      int slot = rowBase + wm*64 + mt*16 + r0 + hh*8;
      __half* hrow = g_h16 + ((size_t)e*CAP + slot)*HIDX + nBase + wn*32;
      #pragma unroll
      for (int nt=0; nt<4; ++nt){
        float g0 = acc[mt][nt][hh*2+0],   g1 = acc[mt][nt][hh*2+1];
        float u0 = acc[mt][nt+4][hh*2+0], u1 = acc[mt][nt+4][hh*2+1];
        float h0 = g0/(1.f+__expf(-g0))*u0;
        float h1 = g1/(1.f+__expf(-g1))*u1;
        *reinterpret_cast<__half2*>(hrow + nt*8 + c0) = __floats2half2_rn(h0,h1);
      }
    }
  }
}

// =============== GEMM 2 (TMA): y[e][slot] = w * (hidden Dᵀ) ====================
// BM=256, BN=128, BK=64; warps 4m x 2n; 4-stage TMA; dense g_y stores.
__global__ __launch_bounds__(256,1) void gemm_down(){
  extern __shared__ char smraw[];
  __shared__ __align__(8) uint64_t full[NSTG], empty[NSTG];
  const int e = blockIdx.z;
  const int cntE = g_cnt[e];
  const int rowBase = blockIdx.x*256;
  if (rowBase >= cntE) return;
  const int nBase = blockIdx.y*128;
  const int tid = threadIdx.x, lane = tid&31, warp = tid>>5;
  const int wm = warp>>1, wn = warp&1;
  const uint32_t base = (sptr(smraw)+1023u) & ~1023u;
  const int KT = HIDX/64;

  if (tid==0){
    #pragma unroll
    for (int s=0;s<NSTG;s++){ mbar_init(sptr(&full[s]),1); mbar_init(sptr(&empty[s]),256); }
    asm volatile("fence.mbarrier_init.release.cluster;" ::: "memory");
  }
  __syncthreads();

  auto issue = [&](int ld){
    uint32_t sa = base + (ld%NSTG)*STAGE_BYTES;
    uint32_t bar = sptr(&full[ld%NSTG]);
    mbar_expect(bar, STAGE_BYTES);
    tma2d(sa,       &g_tmap[3], ld*64, e*CAP + rowBase, bar);
    tma2d(sa+32768, &g_tmap[4], ld*64, e*DIMX + nBase,  bar);
  };
  if (tid==0){ issue(0); issue(1); issue(2); }

  float acc[4][8][4];
  #pragma unroll
  for (int i=0;i<4;i++)
    #pragma unroll
    for (int j=0;j<8;j++)
      #pragma unroll
      for (int k=0;k<4;k++) acc[i][j][k]=0.f;

  for (int kt=0; kt<KT; ++kt){
    const int s = kt%NSTG;
    if (tid==0){
      int ld = kt + (NSTG-1);
      if (ld < KT){
        if (ld >= NSTG) mbar_wait(sptr(&empty[ld%NSTG]), ((ld/NSTG)-1)&1);
        issue(ld);
      }
    }
    mbar_wait(sptr(&full[s]), (kt/NSTG)&1);
    const uint32_t bA = base + s*STAGE_BYTES;
    const uint32_t bB = bA + 32768;
    #pragma unroll
    for (int ks=0; ks<4; ++ks){
      uint32_t a[4][4];
      #pragma unroll
      for (int mt=0; mt<4; ++mt){
        int r = wm*64 + mt*16 + (lane&15);
        ldm4(a[mt][0],a[mt][1],a[mt][2],a[mt][3], bA + swoff(r, ks*2 + (lane>>4)));
      }
      uint32_t b[4][4];
      #pragma unroll
      for (int j=0; j<4; ++j){
        int r = wn*64 + j*16 + (lane&7) + ((lane>>4)<<3);
        ldm4(b[j][0],b[j][1],b[j][2],b[j][3], bB + swoff(r, ks*2 + ((lane>>3)&1)));
      }
      #pragma unroll
      for (int mt=0; mt<4; ++mt){
        #pragma unroll
        for (int nt=0; nt<8; ++nt){
          int j = nt>>1, p = (nt&1)*2;
          mma16816(acc[mt][nt][0],acc[mt][nt][1],acc[mt][nt][2],acc[mt][nt][3],
                   a[mt][0],a[mt][1],a[mt][2],a[mt][3], b[j][p], b[j][p+1]);
        }
      }
    }
    mbar_arrive(sptr(&empty[s]));
  }

  // epilogue: scale by routing weight, dense store into g_y
  const int r0 = lane>>2, c0 = (lane&3)*2;
  #pragma unroll
  for (int mt=0; mt<4; ++mt){
    #pragma unroll
    for (int hh=0; hh<2; ++hh){
      int slot = rowBase + wm*64 + mt*16 + r0 + hh*8;
      float w = g_twf[e*CAP+slot];
      float* yrow = g_y + ((size_t)e*CAP + slot)*DIMX + nBase + wn*64;
      #pragma unroll
      for (int nt=0; nt<8; ++nt){
        float2 v = make_float2(acc[mt][nt][hh*2+0]*w, acc[mt][nt][hh*2+1]*w);
        *reinterpret_cast<float2*>(yrow + nt*8 + c0) = v;
      }
    }
  }
}

// ---------------- gather: out[t] = y[pos0] + y[pos1] + y[shared] --------------
__global__ void gather_k(float4* __restrict__ out){
  int i = blockIdx.x*blockDim.x + threadIdx.x;
  int t = i >> 8;
  int c = i & 255;
  const float4* Y = reinterpret_cast<const float4*>(g_y);
  float4 a = Y[(size_t)g_pos[2*t]  *256 + c];
  float4 b = Y[(size_t)g_pos[2*t+1]*256 + c];
  float4 s = Y[((size_t)NE*CAP + t)*256 + c];
  out[i] = make_float4(a.x+b.x+s.x, a.y+b.y+s.y, a.z+b.z+s.z, a.w+b.w+s.w);
}

// ---------------- host-side tensormap setup -----------------------------------
typedef CUresult (*EncodeFn)(CUtensorMap*, CUtensorMapDataType, cuuint32_t, void*,
                             const cuuint64_t*, const cuuint64_t*, const cuuint32_t*,
                             const cuuint32_t*, CUtensorMapInterleave, CUtensorMapSwizzle,
                             CUtensorMapL2promotion, CUtensorMapFloatOOBfill);

static void encode2d(EncodeFn fn, CUtensorMap* tm, void* ptr,
                     uint64_t cols, uint64_t rows, uint32_t boxc, uint32_t boxr){
  cuuint64_t dims[2]    = { cols, rows };
  cuuint64_t strides[1] = { cols * 2 };
  cuuint32_t box[2]     = { boxc, boxr };
  cuuint32_t estr[2]    = { 1, 1 };
  fn(tm, CU_TENSOR_MAP_DATA_TYPE_FLOAT16, 2, ptr, dims, strides, box, estr,
     CU_TENSOR_MAP_INTERLEAVE_NONE, CU_TENSOR_MAP_SWIZZLE_128B,
     CU_TENSOR_MAP_L2_PROMOTION_L2_128B, CU_TENSOR_MAP_FLOAT_OOB_FILL_NONE);
}

extern "C" void kernel_launch(void* const* d_in, const int* in_sizes, int n_in,
                              void* d_out, int out_size){
  const float* x  = (const float*)d_in[0];
  const float* rw = (const float*)d_in[1];
  const float* eb = (const float*)d_in[2];
  const float* gw = (const float*)d_in[3];
  const float* uw = (const float*)d_in[4];
  const float* dw = (const float*)d_in[5];
  const float* sg = (const float*)d_in[6];
  const float* su = (const float*)d_in[7];
  const float* sd = (const float*)d_in[8];
  float* out = (float*)d_out;
  (void)in_sizes; (void)n_in; (void)out_size;

  static bool setup_done = false;
  if (!setup_done){
    cudaFuncSetAttribute(gemm_gateup, cudaFuncAttributeMaxDynamicSharedMemorySize, SMEM_DYN);
    cudaFuncSetAttribute(gemm_down,   cudaFuncAttributeMaxDynamicSharedMemorySize, SMEM_DYN);
    void* fn = nullptr;
    cudaDriverEntryPointQueryResult qr;
    cudaGetDriverEntryPoint("cuTensorMapEncodeTiled", &fn, cudaEnableDefault, &qr);
    EncodeFn enc = (EncodeFn)fn;
    void *p_xs, *p_wg, *p_wu, *p_wd, *p_h;
    cudaGetSymbolAddress(&p_xs, g_xs);
    cudaGetSymbolAddress(&p_wg, g_wg);
    cudaGetSymbolAddress(&p_wu, g_wu);
    cudaGetSymbolAddress(&p_wd, g_wd);
    cudaGetSymbolAddress(&p_h,  g_h16);
    static CUtensorMap h_tm[5];
    encode2d(enc, &h_tm[0], p_xs, DIMX, (uint64_t)NEX*CAP,  64, 256);  // gu A
    encode2d(enc, &h_tm[1], p_wg, DIMX, (uint64_t)NEX*HIDX, 64, 64);   // gu gate
    encode2d(enc, &h_tm[2], p_wu, DIMX, (uint64_t)NEX*HIDX, 64, 64);   // gu up
    encode2d(enc, &h_tm[3], p_h,  HIDX, (uint64_t)NEX*CAP,  64, 256);  // dn A
    encode2d(enc, &h_tm[4], p_wd, HIDX, (uint64_t)NEX*DIMX, 64, 128);  // dn B
    cudaMemcpyToSymbolAsync(g_tmap, h_tm, 5*sizeof(CUtensorMap), 0,
                            cudaMemcpyHostToDevice, 0);
    setup_done = true;
  }

  // launches: 0=cvt_a 1=cvt_b 2=init 3=router 4=scatter 5=gateup(<-ncu) 6=down 7=gather
  {
    long n4a = 2L*NEX*HD/4;
    cvt_a<<<(unsigned)((n4a+255)/256), 256>>>(gw, uw, sg, su);
    long n4b = (long)NEX*HD/4;
    cvt_b<<<(unsigned)((n4b+255)/256), 256>>>(dw, sd);
  }
  init_k<<<TTOK/256, 256>>>();
  router_k<<<TTOK/8, 256>>>(x, rw, eb);
  scatter_x<<<TTOK, 128>>>(x);

  gemm_gateup<<<dim3(CAP/256, HIDX/64, NEX), 256, SMEM_DYN>>>();
  gemm_down  <<<dim3(CAP/256, DIMX/128, NEX), 256, SMEM_DYN>>>();
  gather_k<<<TTOK*1024/4/256, 256>>>((float4*)out);
}

// round 7
// speedup vs baseline: 1.7424x; 1.0767x over previous
#include <cuda_runtime.h>
#include <cuda_fp16.h>
#include <cuda.h>
#include <cstdint>

#define TTOK 8192
#define DIMX 1024
#define HIDX 2816
#define NE 8
#define NEX 9          // 8 routed experts + shared expert as expert 8
#define CAP 8192
#define HD (HIDX*DIMX)

#define NSTG 4
#define STAGE_BYTES 49152              // A 256x128B (32KB) + B 128x128B (16KB)
#define SMEM_DYN (NSTG*STAGE_BYTES + 1024)

// ---------------- scratch (static device globals; no allocations) -------------
__device__ __align__(1024) __half g_xs[(size_t)NEX*CAP*DIMX];   // slot-ordered x
__device__ __align__(1024) __half g_wg[(size_t)NEX*HD];
__device__ __align__(1024) __half g_wu[(size_t)NEX*HD];
__device__ __align__(1024) __half g_wd[(size_t)NEX*HD];
__device__ __align__(1024) __half g_h16[(size_t)NEX*CAP*HIDX];  // hidden acts
__device__ __align__(1024) float  g_y[(size_t)NEX*CAP*DIMX];
__device__ int    g_cnt[NEX];
__device__ float  g_twf[NEX*CAP];
__device__ int    g_pos[2*TTOK];
// tensormaps: [0]=gu_A(g_xs) [1]=gu_G [2]=gu_U [3]=dn_A(g_h16) [4]=dn_B(g_wd)
__device__ __align__(64) CUtensorMap g_tmap[5];

// ---------------- device helpers ----------------------------------------------
__device__ __forceinline__ uint32_t sptr(const void* p){
  return (uint32_t)__cvta_generic_to_shared(p);
}
__device__ __forceinline__ void mbar_init(uint32_t a, uint32_t n){
  asm volatile("mbarrier.init.shared.b64 [%0], %1;" :: "r"(a), "r"(n) : "memory");
}
__device__ __forceinline__ void mbar_arrive(uint32_t a){
  asm volatile("mbarrier.arrive.shared.b64 _, [%0];" :: "r"(a) : "memory");
}
__device__ __forceinline__ void mbar_expect(uint32_t a, uint32_t tx){
  asm volatile("mbarrier.arrive.expect_tx.shared.b64 _, [%0], %1;" :: "r"(a), "r"(tx) : "memory");
}
__device__ __forceinline__ void mbar_wait(uint32_t a, uint32_t parity){
  uint32_t done;
  asm volatile(
    "{\n\t.reg .pred p;\n\t"
    "mbarrier.try_wait.parity.acquire.cta.shared::cta.b64 p, [%1], %2;\n\t"
    "selp.b32 %0, 1, 0, p;\n\t}"
    : "=r"(done) : "r"(a), "r"(parity) : "memory");
  if (!done){
    asm volatile(
      "{\n\t.reg .pred P1;\n\t"
      "WL_%=:\n\t"
      "mbarrier.try_wait.parity.acquire.cta.shared::cta.b64 P1, [%0], %1, 0x989680;\n\t"
      "@P1 bra.uni WD_%=;\n\t"
      "bra.uni WL_%=;\n\t"
      "WD_%=:\n\t}"
      :: "r"(a), "r"(parity) : "memory");
  }
}
__device__ __forceinline__ void tma2d(uint32_t dst, const CUtensorMap* tm,
                                      int cx, int cy, uint32_t bar){
  asm volatile(
    "cp.async.bulk.tensor.2d.shared::cta.global.tile.mbarrier::complete_tx::bytes "
    "[%0], [%1, {%2, %3}], [%4];"
    :: "r"(dst), "l"(tm), "r"(cx), "r"(cy), "r"(bar) : "memory");
}
__device__ __forceinline__ void ldm4(uint32_t &r0,uint32_t &r1,uint32_t &r2,uint32_t &r3,uint32_t addr){
  asm volatile("ldmatrix.sync.aligned.m8n8.x4.shared.b16 {%0,%1,%2,%3}, [%4];\n"
    : "=r"(r0),"=r"(r1),"=r"(r2),"=r"(r3) : "r"(addr));
}
__device__ __forceinline__ void mma16816(float&d0,float&d1,float&d2,float&d3,
   uint32_t a0,uint32_t a1,uint32_t a2,uint32_t a3,uint32_t b0,uint32_t b1){
  asm volatile("mma.sync.aligned.m16n8k16.row.col.f32.f16.f16.f32 "
    "{%0,%1,%2,%3},{%4,%5,%6,%7},{%8,%9},{%0,%1,%2,%3};\n"
    : "+f"(d0),"+f"(d1),"+f"(d2),"+f"(d3)
    : "r"(a0),"r"(a1),"r"(a2),"r"(a3),"r"(b0),"r"(b1));
}
// silu via single-MUFU tanh.approx: x*sigmoid(x), sigmoid(x)=0.5*tanh(0.5x)+0.5
__device__ __forceinline__ float silu_fast(float x){
  float t;
  asm("tanh.approx.f32 %0, %1;" : "=f"(t) : "f"(0.5f*x));
  return x * fmaf(0.5f, t, 0.5f);
}
// SW128 swizzled smem byte offset for row r (128B rows), 16B chunk c
__device__ __forceinline__ uint32_t swoff(int r, int c){
  return (uint32_t)(r*128 + ((c ^ (r&7))<<4));
}

// ---------------- conversions (2 launches total) -------------------------------
// NOTE: dst is the SEGMENT BASE; i is the segment-relative float4 index.
__device__ __forceinline__ void cvt4(__half* dst, const float* __restrict__ src, size_t i){
  float4 v = reinterpret_cast<const float4*>(src)[i];
  __half2* d2 = reinterpret_cast<__half2*>(dst) + 2*i;
  d2[0] = __floats2half2_rn(v.x, v.y);
  d2[1] = __floats2half2_rn(v.z, v.w);
}
// launch 0: gate (gw|sg) + up (uw|su)
__global__ void cvt_a(const float* __restrict__ gw, const float* __restrict__ uw,
                      const float* __restrict__ sg, const float* __restrict__ su){
  size_t i = (size_t)blockIdx.x*blockDim.x + threadIdx.x;   // float4 index
  const size_t Q  = (size_t)NE*HD/4;    // routed portion per tensor
  const size_t QT = (size_t)NEX*HD/4;   // full tensor
  if (i < QT){
    if (i < Q) cvt4(g_wg, gw, i);
    else       cvt4(g_wg + (size_t)NE*HD, sg, i-Q);
  } else {
    size_t j = i - QT;
    if (j < Q) cvt4(g_wu, uw, j);
    else       cvt4(g_wu + (size_t)NE*HD, su, j-Q);
  }
}
// launch 1: down (dw|sd) + init of counts/shared-expert weights
__global__ void cvt_b(const float* __restrict__ dw, const float* __restrict__ sd){
  size_t i = (size_t)blockIdx.x*blockDim.x + threadIdx.x;
  const size_t Q = (size_t)NE*HD/4;
  if (i < Q) cvt4(g_wd, dw, i);
  else       cvt4(g_wd + (size_t)NE*HD, sd, i-Q);
  if (i < NE)  g_cnt[i] = 0;
  if (i == NE) g_cnt[NE] = TTOK;
  if (i < TTOK) g_twf[NE*CAP+i] = 1.0f;
}

// ---------------- router + scatter ---------------------------------------------
__global__ void router_k(const float* __restrict__ x, const float* __restrict__ rw,
                         const float* __restrict__ eb){
  int t = blockIdx.x*8 + (threadIdx.x>>5);
  int lane = threadIdx.x & 31;
  if (t >= TTOK) return;
  const float* xr = x + (size_t)t*DIMX;
  float acc[NE];
  #pragma unroll
  for (int e=0;e<NE;e++) acc[e]=0.f;
  for (int k = lane; k < DIMX; k += 32){
    float xv = xr[k];
    #pragma unroll
    for (int e=0;e<NE;e++) acc[e] = fmaf(xv, rw[e*DIMX+k], acc[e]);
  }
  #pragma unroll
  for (int e=0;e<NE;e++){
    #pragma unroll
    for (int o=16;o>0;o>>=1) acc[e] += __shfl_xor_sync(0xffffffffu, acc[e], o);
  }
  if (lane==0){
    float s[NE];
    #pragma unroll
    for (int e=0;e<NE;e++){
      float l = acc[e] + eb[e];
      s[e] = 1.f / (1.f + __expf(-l));
    }
    int i0=0;
    #pragma unroll
    for (int e=1;e<NE;e++) if (s[e] > s[i0]) i0=e;
    int i1 = (i0==0)?1:0;
    #pragma unroll
    for (int e=0;e<NE;e++) if (e!=i0 && s[e] > s[i1]) i1=e;
    float inv = 1.f / (s[i0]+s[i1]+1e-6f);
    int p0 = atomicAdd(&g_cnt[i0], 1);
    g_twf[i0*CAP+p0]=s[i0]*inv; g_pos[2*t]   = i0*CAP+p0;
    int p1 = atomicAdd(&g_cnt[i1], 1);
    g_twf[i1*CAP+p1]=s[i1]*inv; g_pos[2*t+1] = i1*CAP+p1;
  }
}

__global__ void scatter_x(const float* __restrict__ x){
  int t = blockIdx.x;
  int c = threadIdx.x;         // 128 threads, 8 halves each
  const float4* xr = reinterpret_cast<const float4*>(x + (size_t)t*DIMX) + 2*c;
  float4 v0 = xr[0], v1 = xr[1];
  __half2 h[4] = { __floats2half2_rn(v0.x,v0.y), __floats2half2_rn(v0.z,v0.w),
                   __floats2half2_rn(v1.x,v1.y), __floats2half2_rn(v1.z,v1.w) };
  uint4 pack = *reinterpret_cast<uint4*>(h);
  int p0 = g_pos[2*t], p1 = g_pos[2*t+1], ps = NE*CAP + t;
  uint4* base = reinterpret_cast<uint4*>(g_xs);
  base[(size_t)p0*128 + c] = pack;
  base[(size_t)p1*128 + c] = pack;
  base[(size_t)ps*128 + c] = pack;
}

// =============== GEMM 1 (TMA): hidden = silu(X Gᵀ) * (X Uᵀ) ===================
// BM=256, B tile = 64 gate + 64 up rows, BK=64; warps 4m x 2n; 4-stage TMA.
__global__ __launch_bounds__(256,1) void gemm_gateup(){
  extern __shared__ char smraw[];
  __shared__ __align__(8) uint64_t full[NSTG], empty[NSTG];
  const int e = blockIdx.z;
  const int cntE = g_cnt[e];
  const int rowBase = blockIdx.x*256;
  if (rowBase >= cntE) return;
  const int nBase = blockIdx.y*64;
  const int tid = threadIdx.x, lane = tid&31, warp = tid>>5;
  const int wm = warp>>1, wn = warp&1;
  const uint32_t base = (sptr(smraw)+1023u) & ~1023u;
  const int KT = DIMX/64;

  if (tid==0){
    #pragma unroll
    for (int s=0;s<NSTG;s++){ mbar_init(sptr(&full[s]),1); mbar_init(sptr(&empty[s]),256); }
    asm volatile("fence.mbarrier_init.release.cluster;" ::: "memory");
  }
  __syncthreads();

  auto issue = [&](int ld){
    uint32_t sa = base + (ld%NSTG)*STAGE_BYTES;
    uint32_t bar = sptr(&full[ld%NSTG]);
    mbar_expect(bar, STAGE_BYTES);
    tma2d(sa,           &g_tmap[0], ld*64, e*CAP + rowBase, bar);
    tma2d(sa+32768,     &g_tmap[1], ld*64, e*HIDX + nBase,  bar);
    tma2d(sa+32768+8192,&g_tmap[2], ld*64, e*HIDX + nBase,  bar);
  };
  if (tid==0){ issue(0); issue(1); issue(2); }

  float acc[4][8][4];
  #pragma unroll
  for (int i=0;i<4;i++)
    #pragma unroll
    for (int j=0;j<8;j++)
      #pragma unroll
      for (int k=0;k<4;k++) acc[i][j][k]=0.f;

  for (int kt=0; kt<KT; ++kt){
    const int s = kt%NSTG;
    if (tid==0){
      int ld = kt + (NSTG-1);
      if (ld < KT){
        if (ld >= NSTG) mbar_wait(sptr(&empty[ld%NSTG]), ((ld/NSTG)-1)&1);
        issue(ld);
      }
    }
    mbar_wait(sptr(&full[s]), (kt/NSTG)&1);
    const uint32_t bA = base + s*STAGE_BYTES;
    const uint32_t bB = bA + 32768;
    #pragma unroll
    for (int ks=0; ks<4; ++ks){
      uint32_t a[4][4];
      #pragma unroll
      for (int mt=0; mt<4; ++mt){
        int r = wm*64 + mt*16 + (lane&15);
        ldm4(a[mt][0],a[mt][1],a[mt][2],a[mt][3], bA + swoff(r, ks*2 + (lane>>4)));
      }
      uint32_t b[4][4];   // j 0..1: gate, j 2..3: up
      #pragma unroll
      for (int j=0; j<4; ++j){
        int r = ((j>>1)<<6) + wn*32 + (j&1)*16 + (lane&7) + ((lane>>4)<<3);
        ldm4(b[j][0],b[j][1],b[j][2],b[j][3], bB + swoff(r, ks*2 + ((lane>>3)&1)));
      }
      #pragma unroll
      for (int mt=0; mt<4; ++mt){
        #pragma unroll
        for (int nt=0; nt<8; ++nt){   // nt 0..3 gate, 4..7 up
          int j = nt>>1, p = (nt&1)*2;
          mma16816(acc[mt][nt][0],acc[mt][nt][1],acc[mt][nt][2],acc[mt][nt][3],
                   a[mt][0],a[mt][1],a[mt][2],a[mt][3], b[j][p], b[j][p+1]);
        }
      }
    }
    mbar_arrive(sptr(&empty[s]));
  }

  // epilogue: silu(gate)*up -> fp16 hidden (tanh.approx: 1 MUFU per element)
  const int r0 = lane>>2, c0 = (lane&3)*2;
  #pragma unroll
  for (int mt=0; mt<4; ++mt){
    #pragma unroll
    for (int hh=0; hh<2; ++hh){
      int slot = rowBase + wm*64 + mt*16 + r0 + hh*8;
      __half* hrow = g_h16 + ((size_t)e*CAP + slot)*HIDX + nBase + wn*32;
      #pragma unroll
      for (int nt=0; nt<4; ++nt){
        float g0 = acc[mt][nt][hh*2+0],   g1 = acc[mt][nt][hh*2+1];
        float u0 = acc[mt][nt+4][hh*2+0], u1 = acc[mt][nt+4][hh*2+1];
        float h0 = silu_fast(g0)*u0;
        float h1 = silu_fast(g1)*u1;
        *reinterpret_cast<__half2*>(hrow + nt*8 + c0) = __floats2half2_rn(h0,h1);
      }
    }
  }
}

// =============== GEMM 2 (TMA): y[e][slot] = w * (hidden Dᵀ) ====================
// BM=256, BN=128, BK=64; warps 4m x 2n; 4-stage TMA; dense g_y stores.
__global__ __launch_bounds__(256,1) void gemm_down(){
  extern __shared__ char smraw[];
  __shared__ __align__(8) uint64_t full[NSTG], empty[NSTG];
  const int e = blockIdx.z;
  const int cntE = g_cnt[e];
  const int rowBase = blockIdx.x*256;
  if (rowBase >= cntE) return;
  const int nBase = blockIdx.y*128;
  const int tid = threadIdx.x, lane = tid&31, warp = tid>>5;
  const int wm = warp>>1, wn = warp&1;
  const uint32_t base = (sptr(smraw)+1023u) & ~1023u;
  const int KT = HIDX/64;

  if (tid==0){
    #pragma unroll
    for (int s=0;s<NSTG;s++){ mbar_init(sptr(&full[s]),1); mbar_init(sptr(&empty[s]),256); }
    asm volatile("fence.mbarrier_init.release.cluster;" ::: "memory");
  }
  __syncthreads();

  auto issue = [&](int ld){
    uint32_t sa = base + (ld%NSTG)*STAGE_BYTES;
    uint32_t bar = sptr(&full[ld%NSTG]);
    mbar_expect(bar, STAGE_BYTES);
    tma2d(sa,       &g_tmap[3], ld*64, e*CAP + rowBase, bar);
    tma2d(sa+32768, &g_tmap[4], ld*64, e*DIMX + nBase,  bar);
  };
  if (tid==0){ issue(0); issue(1); issue(2); }

  float acc[4][8][4];
  #pragma unroll
  for (int i=0;i<4;i++)
    #pragma unroll
    for (int j=0;j<8;j++)
      #pragma unroll
      for (int k=0;k<4;k++) acc[i][j][k]=0.f;

  for (int kt=0; kt<KT; ++kt){
    const int s = kt%NSTG;
    if (tid==0){
      int ld = kt + (NSTG-1);
      if (ld < KT){
        if (ld >= NSTG) mbar_wait(sptr(&empty[ld%NSTG]), ((ld/NSTG)-1)&1);
        issue(ld);
      }
    }
    mbar_wait(sptr(&full[s]), (kt/NSTG)&1);
    const uint32_t bA = base + s*STAGE_BYTES;
    const uint32_t bB = bA + 32768;
    #pragma unroll
    for (int ks=0; ks<4; ++ks){
      uint32_t a[4][4];
      #pragma unroll
      for (int mt=0; mt<4; ++mt){
        int r = wm*64 + mt*16 + (lane&15);
        ldm4(a[mt][0],a[mt][1],a[mt][2],a[mt][3], bA + swoff(r, ks*2 + (lane>>4)));
      }
      uint32_t b[4][4];
      #pragma unroll
      for (int j=0; j<4; ++j){
        int r = wn*64 + j*16 + (lane&7) + ((lane>>4)<<3);
        ldm4(b[j][0],b[j][1],b[j][2],b[j][3], bB + swoff(r, ks*2 + ((lane>>3)&1)));
      }
      #pragma unroll
      for (int mt=0; mt<4; ++mt){
        #pragma unroll
        for (int nt=0; nt<8; ++nt){
          int j = nt>>1, p = (nt&1)*2;
          mma16816(acc[mt][nt][0],acc[mt][nt][1],acc[mt][nt][2],acc[mt][nt][3],
                   a[mt][0],a[mt][1],a[mt][2],a[mt][3], b[j][p], b[j][p+1]);
        }
      }
    }
    mbar_arrive(sptr(&empty[s]));
  }

  // epilogue: scale by routing weight, dense store into g_y
  const int r0 = lane>>2, c0 = (lane&3)*2;
  #pragma unroll
  for (int mt=0; mt<4; ++mt){
    #pragma unroll
    for (int hh=0; hh<2; ++hh){
      int slot = rowBase + wm*64 + mt*16 + r0 + hh*8;
      float w = g_twf[e*CAP+slot];
      float* yrow = g_y + ((size_t)e*CAP + slot)*DIMX + nBase + wn*64;
      #pragma unroll
      for (int nt=0; nt<8; ++nt){
        float2 v = make_float2(acc[mt][nt][hh*2+0]*w, acc[mt][nt][hh*2+1]*w);
        *reinterpret_cast<float2*>(yrow + nt*8 + c0) = v;
      }
    }
  }
}

// ---------------- gather: out[t] = y[pos0] + y[pos1] + y[shared] --------------
__global__ void gather_k(float4* __restrict__ out){
  int i = blockIdx.x*blockDim.x + threadIdx.x;
  int t = i >> 8;
  int c = i & 255;
  const float4* Y = reinterpret_cast<const float4*>(g_y);
  float4 a = Y[(size_t)g_pos[2*t]  *256 + c];
  float4 b = Y[(size_t)g_pos[2*t+1]*256 + c];
  float4 s = Y[((size_t)NE*CAP + t)*256 + c];
  out[i] = make_float4(a.x+b.x+s.x, a.y+b.y+s.y, a.z+b.z+s.z, a.w+b.w+s.w);
}

// ---------------- host-side tensormap setup -----------------------------------
typedef CUresult (*EncodeFn)(CUtensorMap*, CUtensorMapDataType, cuuint32_t, void*,
                             const cuuint64_t*, const cuuint64_t*, const cuuint32_t*,
                             const cuuint32_t*, CUtensorMapInterleave, CUtensorMapSwizzle,
                             CUtensorMapL2promotion, CUtensorMapFloatOOBfill);

static void encode2d(EncodeFn fn, CUtensorMap* tm, void* ptr,
                     uint64_t cols, uint64_t rows, uint32_t boxc, uint32_t boxr){
  cuuint64_t dims[2]    = { cols, rows };
  cuuint64_t strides[1] = { cols * 2 };
  cuuint32_t box[2]     = { boxc, boxr };
  cuuint32_t estr[2]    = { 1, 1 };
  fn(tm, CU_TENSOR_MAP_DATA_TYPE_FLOAT16, 2, ptr, dims, strides, box, estr,
     CU_TENSOR_MAP_INTERLEAVE_NONE, CU_TENSOR_MAP_SWIZZLE_128B,
     CU_TENSOR_MAP_L2_PROMOTION_L2_128B, CU_TENSOR_MAP_FLOAT_OOB_FILL_NONE);
}

extern "C" void kernel_launch(void* const* d_in, const int* in_sizes, int n_in,
                              void* d_out, int out_size){
  const float* x  = (const float*)d_in[0];
  const float* rw = (const float*)d_in[1];
  const float* eb = (const float*)d_in[2];
  const float* gw = (const float*)d_in[3];
  const float* uw = (const float*)d_in[4];
  const float* dw = (const float*)d_in[5];
  const float* sg = (const float*)d_in[6];
  const float* su = (const float*)d_in[7];
  const float* sd = (const float*)d_in[8];
  float* out = (float*)d_out;
  (void)in_sizes; (void)n_in; (void)out_size;

  static bool setup_done = false;
  if (!setup_done){
    cudaFuncSetAttribute(gemm_gateup, cudaFuncAttributeMaxDynamicSharedMemorySize, SMEM_DYN);
    cudaFuncSetAttribute(gemm_down,   cudaFuncAttributeMaxDynamicSharedMemorySize, SMEM_DYN);
    void* fn = nullptr;
    cudaDriverEntryPointQueryResult qr;
    cudaGetDriverEntryPoint("cuTensorMapEncodeTiled", &fn, cudaEnableDefault, &qr);
    EncodeFn enc = (EncodeFn)fn;
    void *p_xs, *p_wg, *p_wu, *p_wd, *p_h;
    cudaGetSymbolAddress(&p_xs, g_xs);
    cudaGetSymbolAddress(&p_wg, g_wg);
    cudaGetSymbolAddress(&p_wu, g_wu);
    cudaGetSymbolAddress(&p_wd, g_wd);
    cudaGetSymbolAddress(&p_h,  g_h16);
    static CUtensorMap h_tm[5];
    encode2d(enc, &h_tm[0], p_xs, DIMX, (uint64_t)NEX*CAP,  64, 256);  // gu A
    encode2d(enc, &h_tm[1], p_wg, DIMX, (uint64_t)NEX*HIDX, 64, 64);   // gu gate
    encode2d(enc, &h_tm[2], p_wu, DIMX, (uint64_t)NEX*HIDX, 64, 64);   // gu up
    encode2d(enc, &h_tm[3], p_h,  HIDX, (uint64_t)NEX*CAP,  64, 256);  // dn A
    encode2d(enc, &h_tm[4], p_wd, HIDX, (uint64_t)NEX*DIMX, 64, 128);  // dn B
    cudaMemcpyToSymbolAsync(g_tmap, h_tm, 5*sizeof(CUtensorMap), 0,
                            cudaMemcpyHostToDevice, 0);
    setup_done = true;
  }

  {
    long n4a = 2L*NEX*HD/4;
    cvt_a<<<(unsigned)((n4a+255)/256), 256>>>(gw, uw, sg, su);
    long n4b = (long)NEX*HD/4;
    cvt_b<<<(unsigned)((n4b+255)/256), 256>>>(dw, sd);
  }
  router_k<<<TTOK/8, 256>>>(x, rw, eb);
  scatter_x<<<TTOK, 128>>>(x);

  gemm_gateup<<<dim3(CAP/256, HIDX/64, NEX), 256, SMEM_DYN>>>();
  gemm_down  <<<dim3(CAP/256, DIMX/128, NEX), 256, SMEM_DYN>>>();
  gather_k<<<TTOK*1024/4/256, 256>>>((float4*)out);
}

// round 8
// speedup vs baseline: 1.8537x; 1.0639x over previous
#include <cuda_runtime.h>
#include <cuda_fp16.h>
#include <cuda.h>
#include <cstdint>

#define TTOK 8192
#define DIMX 1024
#define HIDX 2816
#define NE 8
#define NEX 9          // 8 routed experts + shared expert as expert 8
#define CAP 8192
#define HD (HIDX*DIMX)

#define NSTG 3
#define STAGE_BYTES 32768              // A 128x128B (16KB) + B 128x128B (16KB)
#define SMEM_DYN (NSTG*STAGE_BYTES + 1024)

// ---------------- scratch (static device globals; no allocations) -------------
__device__ __align__(1024) __half g_xs[(size_t)NEX*CAP*DIMX];   // slot-ordered x
__device__ __align__(1024) __half g_wg[(size_t)NEX*HD];
__device__ __align__(1024) __half g_wu[(size_t)NEX*HD];
__device__ __align__(1024) __half g_wd[(size_t)NEX*HD];
__device__ __align__(1024) __half g_h16[(size_t)NEX*CAP*HIDX];  // hidden acts
__device__ __align__(1024) float  g_y[(size_t)NEX*CAP*DIMX];
__device__ int    g_cnt[NEX];
__device__ float  g_twf[NEX*CAP];
__device__ int    g_pos[2*TTOK];
// tensormaps: [0]=gu_A(g_xs) [1]=gu_G [2]=gu_U [3]=dn_A(g_h16) [4]=dn_B(g_wd)
__device__ __align__(64) CUtensorMap g_tmap[5];

// ---------------- device helpers ----------------------------------------------
__device__ __forceinline__ uint32_t sptr(const void* p){
  return (uint32_t)__cvta_generic_to_shared(p);
}
__device__ __forceinline__ void mbar_init(uint32_t a, uint32_t n){
  asm volatile("mbarrier.init.shared.b64 [%0], %1;" :: "r"(a), "r"(n) : "memory");
}
__device__ __forceinline__ void mbar_arrive(uint32_t a){
  asm volatile("mbarrier.arrive.shared.b64 _, [%0];" :: "r"(a) : "memory");
}
__device__ __forceinline__ void mbar_expect(uint32_t a, uint32_t tx){
  asm volatile("mbarrier.arrive.expect_tx.shared.b64 _, [%0], %1;" :: "r"(a), "r"(tx) : "memory");
}
__device__ __forceinline__ void mbar_wait(uint32_t a, uint32_t parity){
  uint32_t done;
  asm volatile(
    "{\n\t.reg .pred p;\n\t"
    "mbarrier.try_wait.parity.acquire.cta.shared::cta.b64 p, [%1], %2;\n\t"
    "selp.b32 %0, 1, 0, p;\n\t}"
    : "=r"(done) : "r"(a), "r"(parity) : "memory");
  if (!done){
    asm volatile(
      "{\n\t.reg .pred P1;\n\t"
      "WL_%=:\n\t"
      "mbarrier.try_wait.parity.acquire.cta.shared::cta.b64 P1, [%0], %1, 0x989680;\n\t"
      "@P1 bra.uni WD_%=;\n\t"
      "bra.uni WL_%=;\n\t"
      "WD_%=:\n\t}"
      :: "r"(a), "r"(parity) : "memory");
  }
}
__device__ __forceinline__ void tma2d(uint32_t dst, const CUtensorMap* tm,
                                      int cx, int cy, uint32_t bar){
  asm volatile(
    "cp.async.bulk.tensor.2d.shared::cta.global.tile.mbarrier::complete_tx::bytes "
    "[%0], [%1, {%2, %3}], [%4];"
    :: "r"(dst), "l"(tm), "r"(cx), "r"(cy), "r"(bar) : "memory");
}
__device__ __forceinline__ void ldm4(uint32_t &r0,uint32_t &r1,uint32_t &r2,uint32_t &r3,uint32_t addr){
  asm volatile("ldmatrix.sync.aligned.m8n8.x4.shared.b16 {%0,%1,%2,%3}, [%4];\n"
    : "=r"(r0),"=r"(r1),"=r"(r2),"=r"(r3) : "r"(addr));
}
__device__ __forceinline__ void mma16816(float&d0,float&d1,float&d2,float&d3,
   uint32_t a0,uint32_t a1,uint32_t a2,uint32_t a3,uint32_t b0,uint32_t b1){
  asm volatile("mma.sync.aligned.m16n8k16.row.col.f32.f16.f16.f32 "
    "{%0,%1,%2,%3},{%4,%5,%6,%7},{%8,%9},{%0,%1,%2,%3};\n"
    : "+f"(d0),"+f"(d1),"+f"(d2),"+f"(d3)
    : "r"(a0),"r"(a1),"r"(a2),"r"(a3),"r"(b0),"r"(b1));
}
// silu via single-MUFU tanh.approx: x*sigmoid(x), sigmoid(x)=0.5*tanh(0.5x)+0.5
__device__ __forceinline__ float silu_fast(float x){
  float t;
  asm("tanh.approx.f32 %0, %1;" : "=f"(t) : "f"(0.5f*x));
  return x * fmaf(0.5f, t, 0.5f);
}
// SW128 swizzled smem byte offset for row r (128B rows), 16B chunk c
__device__ __forceinline__ uint32_t swoff(int r, int c){
  return (uint32_t)(r*128 + ((c ^ (r&7))<<4));
}

// ---------------- conversion (single launch, 2D grid) --------------------------
__device__ __forceinline__ void cvt4(__half* dst, const float* __restrict__ src, size_t i){
  float4 v = reinterpret_cast<const float4*>(src)[i];
  __half2* d2 = reinterpret_cast<__half2*>(dst) + 2*i;
  d2[0] = __floats2half2_rn(v.x, v.y);
  d2[1] = __floats2half2_rn(v.z, v.w);
}
__global__ void cvt_all(const float* __restrict__ gw, const float* __restrict__ uw,
                        const float* __restrict__ dw, const float* __restrict__ sg,
                        const float* __restrict__ su, const float* __restrict__ sd){
  size_t j = (size_t)blockIdx.x*blockDim.x + threadIdx.x;  // float4 idx within tensor
  const size_t Q = (size_t)NE*HD/4;
  switch (blockIdx.y){
    case 0:
      if (j < Q) cvt4(g_wg, gw, j);
      else       cvt4(g_wg + (size_t)NE*HD, sg, j-Q);
      // fold init here (once, seg 0)
      if (j < NE)  g_cnt[j] = 0;
      if (j == NE) g_cnt[NE] = TTOK;
      if (j < TTOK) g_twf[NE*CAP+j] = 1.0f;
      break;
    case 1:
      if (j < Q) cvt4(g_wu, uw, j);
      else       cvt4(g_wu + (size_t)NE*HD, su, j-Q);
      break;
    default:
      if (j < Q) cvt4(g_wd, dw, j);
      else       cvt4(g_wd + (size_t)NE*HD, sd, j-Q);
      break;
  }
}

// ---------------- router + scatter ---------------------------------------------
__global__ void router_k(const float* __restrict__ x, const float* __restrict__ rw,
                         const float* __restrict__ eb){
  int t = blockIdx.x*8 + (threadIdx.x>>5);
  int lane = threadIdx.x & 31;
  if (t >= TTOK) return;
  const float* xr = x + (size_t)t*DIMX;
  float acc[NE];
  #pragma unroll
  for (int e=0;e<NE;e++) acc[e]=0.f;
  for (int k = lane; k < DIMX; k += 32){
    float xv = xr[k];
    #pragma unroll
    for (int e=0;e<NE;e++) acc[e] = fmaf(xv, rw[e*DIMX+k], acc[e]);
  }
  #pragma unroll
  for (int e=0;e<NE;e++){
    #pragma unroll
    for (int o=16;o>0;o>>=1) acc[e] += __shfl_xor_sync(0xffffffffu, acc[e], o);
  }
  if (lane==0){
    float s[NE];
    #pragma unroll
    for (int e=0;e<NE;e++){
      float l = acc[e] + eb[e];
      s[e] = 1.f / (1.f + __expf(-l));
    }
    int i0=0;
    #pragma unroll
    for (int e=1;e<NE;e++) if (s[e] > s[i0]) i0=e;
    int i1 = (i0==0)?1:0;
    #pragma unroll
    for (int e=0;e<NE;e++) if (e!=i0 && s[e] > s[i1]) i1=e;
    float inv = 1.f / (s[i0]+s[i1]+1e-6f);
    int p0 = atomicAdd(&g_cnt[i0], 1);
    g_twf[i0*CAP+p0]=s[i0]*inv; g_pos[2*t]   = i0*CAP+p0;
    int p1 = atomicAdd(&g_cnt[i1], 1);
    g_twf[i1*CAP+p1]=s[i1]*inv; g_pos[2*t+1] = i1*CAP+p1;
  }
}

__global__ void scatter_x(const float* __restrict__ x){
  int t = blockIdx.x;
  int c = threadIdx.x;         // 128 threads, 8 halves each
  const float4* xr = reinterpret_cast<const float4*>(x + (size_t)t*DIMX) + 2*c;
  float4 v0 = xr[0], v1 = xr[1];
  __half2 h[4] = { __floats2half2_rn(v0.x,v0.y), __floats2half2_rn(v0.z,v0.w),
                   __floats2half2_rn(v1.x,v1.y), __floats2half2_rn(v1.z,v1.w) };
  uint4 pack = *reinterpret_cast<uint4*>(h);
  int p0 = g_pos[2*t], p1 = g_pos[2*t+1], ps = NE*CAP + t;
  uint4* base = reinterpret_cast<uint4*>(g_xs);
  base[(size_t)p0*128 + c] = pack;
  base[(size_t)p1*128 + c] = pack;
  base[(size_t)ps*128 + c] = pack;
}

// =============== GEMM 1 (TMA): hidden = silu(X Gᵀ) * (X Uᵀ) ===================
// BM=128, B tile = 64 gate + 64 up rows, BK=64; warps 4m x 2n; 3-stage TMA;
// 2 CTAs/SM so fill/epilogue of one CTA overlaps mainloop of the other.
__global__ __launch_bounds__(256,2) void gemm_gateup(){
  extern __shared__ char smraw[];
  __shared__ __align__(8) uint64_t full[NSTG], empty[NSTG];
  const int e = blockIdx.z;
  const int cntE = g_cnt[e];
  const int rowBase = blockIdx.x*128;
  if (rowBase >= cntE) return;
  const int nBase = blockIdx.y*64;
  const int tid = threadIdx.x, lane = tid&31, warp = tid>>5;
  const int wm = warp>>1, wn = warp&1;
  const uint32_t base = (sptr(smraw)+1023u) & ~1023u;
  const int KT = DIMX/64;   // 16

  if (tid==0){
    #pragma unroll
    for (int s=0;s<NSTG;s++){ mbar_init(sptr(&full[s]),1); mbar_init(sptr(&empty[s]),256); }
    asm volatile("fence.mbarrier_init.release.cluster;" ::: "memory");
  }
  __syncthreads();

  auto issue = [&](int ld){
    uint32_t sa = base + (ld%NSTG)*STAGE_BYTES;
    uint32_t bar = sptr(&full[ld%NSTG]);
    mbar_expect(bar, STAGE_BYTES);
    tma2d(sa,            &g_tmap[0], ld*64, e*CAP + rowBase, bar);
    tma2d(sa+16384,      &g_tmap[1], ld*64, e*HIDX + nBase,  bar);
    tma2d(sa+16384+8192, &g_tmap[2], ld*64, e*HIDX + nBase,  bar);
  };
  if (tid==0){ issue(0); issue(1); }

  float acc[2][8][4];
  #pragma unroll
  for (int i=0;i<2;i++)
    #pragma unroll
    for (int j=0;j<8;j++)
      #pragma unroll
      for (int k=0;k<4;k++) acc[i][j][k]=0.f;

  for (int kt=0; kt<KT; ++kt){
    const int s = kt%NSTG;
    if (tid==0){
      int ld = kt + (NSTG-1);
      if (ld < KT){
        if (ld >= NSTG) mbar_wait(sptr(&empty[ld%NSTG]), ((ld/NSTG)-1)&1);
        issue(ld);
      }
    }
    mbar_wait(sptr(&full[s]), (kt/NSTG)&1);
    const uint32_t bA = base + s*STAGE_BYTES;
    const uint32_t bB = bA + 16384;
    #pragma unroll
    for (int ks=0; ks<4; ++ks){
      uint32_t a[2][4];
      #pragma unroll
      for (int mt=0; mt<2; ++mt){
        int r = wm*32 + mt*16 + (lane&15);
        ldm4(a[mt][0],a[mt][1],a[mt][2],a[mt][3], bA + swoff(r, ks*2 + (lane>>4)));
      }
      uint32_t b[4][4];   // j 0..1: gate, j 2..3: up
      #pragma unroll
      for (int j=0; j<4; ++j){
        int r = ((j>>1)<<6) + wn*32 + (j&1)*16 + (lane&7) + ((lane>>4)<<3);
        ldm4(b[j][0],b[j][1],b[j][2],b[j][3], bB + swoff(r, ks*2 + ((lane>>3)&1)));
      }
      #pragma unroll
      for (int mt=0; mt<2; ++mt){
        #pragma unroll
        for (int nt=0; nt<8; ++nt){   // nt 0..3 gate, 4..7 up
          int j = nt>>1, p = (nt&1)*2;
          mma16816(acc[mt][nt][0],acc[mt][nt][1],acc[mt][nt][2],acc[mt][nt][3],
                   a[mt][0],a[mt][1],a[mt][2],a[mt][3], b[j][p], b[j][p+1]);
        }
      }
    }
    mbar_arrive(sptr(&empty[s]));
  }

  // epilogue: silu(gate)*up -> fp16 hidden (tanh.approx: 1 MUFU per element)
  const int r0 = lane>>2, c0 = (lane&3)*2;
  #pragma unroll
  for (int mt=0; mt<2; ++mt){
    #pragma unroll
    for (int hh=0; hh<2; ++hh){
      int slot = rowBase + wm*32 + mt*16 + r0 + hh*8;
      __half* hrow = g_h16 + ((size_t)e*CAP + slot)*HIDX + nBase + wn*32;
      #pragma unroll
      for (int nt=0; nt<4; ++nt){
        float g0 = acc[mt][nt][hh*2+0],   g1 = acc[mt][nt][hh*2+1];
        float u0 = acc[mt][nt+4][hh*2+0], u1 = acc[mt][nt+4][hh*2+1];
        float h0 = silu_fast(g0)*u0;
        float h1 = silu_fast(g1)*u1;
        *reinterpret_cast<__half2*>(hrow + nt*8 + c0) = __floats2half2_rn(h0,h1);
      }
    }
  }
}

// =============== GEMM 2 (TMA): y[e][slot] = w * (hidden Dᵀ) ====================
// BM=128, BN=128, BK=64; warps 4m x 2n; 3-stage TMA; 2 CTAs/SM.
// Grid: x = n-blocks (fastest) so consecutive CTAs reuse the A tile via L2.
__global__ __launch_bounds__(256,2) void gemm_down(){
  extern __shared__ char smraw[];
  __shared__ __align__(8) uint64_t full[NSTG], empty[NSTG];
  const int e = blockIdx.z;
  const int cntE = g_cnt[e];
  const int rowBase = blockIdx.y*128;
  if (rowBase >= cntE) return;
  const int nBase = blockIdx.x*128;
  const int tid = threadIdx.x, lane = tid&31, warp = tid>>5;
  const int wm = warp>>1, wn = warp&1;
  const uint32_t base = (sptr(smraw)+1023u) & ~1023u;
  const int KT = HIDX/64;   // 44

  if (tid==0){
    #pragma unroll
    for (int s=0;s<NSTG;s++){ mbar_init(sptr(&full[s]),1); mbar_init(sptr(&empty[s]),256); }
    asm volatile("fence.mbarrier_init.release.cluster;" ::: "memory");
  }
  __syncthreads();

  auto issue = [&](int ld){
    uint32_t sa = base + (ld%NSTG)*STAGE_BYTES;
    uint32_t bar = sptr(&full[ld%NSTG]);
    mbar_expect(bar, STAGE_BYTES);
    tma2d(sa,       &g_tmap[3], ld*64, e*CAP + rowBase, bar);
    tma2d(sa+16384, &g_tmap[4], ld*64, e*DIMX + nBase,  bar);
  };
  if (tid==0){ issue(0); issue(1); }

  float acc[2][8][4];
  #pragma unroll
  for (int i=0;i<2;i++)
    #pragma unroll
    for (int j=0;j<8;j++)
      #pragma unroll
      for (int k=0;k<4;k++) acc[i][j][k]=0.f;

  for (int kt=0; kt<KT; ++kt){
    const int s = kt%NSTG;
    if (tid==0){
      int ld = kt + (NSTG-1);
      if (ld < KT){
        if (ld >= NSTG) mbar_wait(sptr(&empty[ld%NSTG]), ((ld/NSTG)-1)&1);
        issue(ld);
      }
    }
    mbar_wait(sptr(&full[s]), (kt/NSTG)&1);
    const uint32_t bA = base + s*STAGE_BYTES;
    const uint32_t bB = bA + 16384;
    #pragma unroll
    for (int ks=0; ks<4; ++ks){
      uint32_t a[2][4];
      #pragma unroll
      for (int mt=0; mt<2; ++mt){
        int r = wm*32 + mt*16 + (lane&15);
        ldm4(a[mt][0],a[mt][1],a[mt][2],a[mt][3], bA + swoff(r, ks*2 + (lane>>4)));
      }
      uint32_t b[4][4];
      #pragma unroll
      for (int j=0; j<4; ++j){
        int r = wn*64 + j*16 + (lane&7) + ((lane>>4)<<3);
        ldm4(b[j][0],b[j][1],b[j][2],b[j][3], bB + swoff(r, ks*2 + ((lane>>3)&1)));
      }
      #pragma unroll
      for (int mt=0; mt<2; ++mt){
        #pragma unroll
        for (int nt=0; nt<8; ++nt){
          int j = nt>>1, p = (nt&1)*2;
          mma16816(acc[mt][nt][0],acc[mt][nt][1],acc[mt][nt][2],acc[mt][nt][3],
                   a[mt][0],a[mt][1],a[mt][2],a[mt][3], b[j][p], b[j][p+1]);
        }
      }
    }
    mbar_arrive(sptr(&empty[s]));
  }

  // epilogue: scale by routing weight, dense store into g_y
  const int r0 = lane>>2, c0 = (lane&3)*2;
  #pragma unroll
  for (int mt=0; mt<2; ++mt){
    #pragma unroll
    for (int hh=0; hh<2; ++hh){
      int slot = rowBase + wm*32 + mt*16 + r0 + hh*8;
      float w = g_twf[e*CAP+slot];
      float* yrow = g_y + ((size_t)e*CAP + slot)*DIMX + nBase + wn*64;
      #pragma unroll
      for (int nt=0; nt<8; ++nt){
        float2 v = make_float2(acc[mt][nt][hh*2+0]*w, acc[mt][nt][hh*2+1]*w);
        *reinterpret_cast<float2*>(yrow + nt*8 + c0) = v;
      }
    }
  }
}

// ---------------- gather: out[t] = y[pos0] + y[pos1] + y[shared] --------------
__global__ void gather_k(float4* __restrict__ out){
  int i = blockIdx.x*blockDim.x + threadIdx.x;
  int t = i >> 8;
  int c = i & 255;
  const float4* Y = reinterpret_cast<const float4*>(g_y);
  float4 a = Y[(size_t)g_pos[2*t]  *256 + c];
  float4 b = Y[(size_t)g_pos[2*t+1]*256 + c];
  float4 s = Y[((size_t)NE*CAP + t)*256 + c];
  out[i] = make_float4(a.x+b.x+s.x, a.y+b.y+s.y, a.z+b.z+s.z, a.w+b.w+s.w);
}

// ---------------- host-side tensormap setup -----------------------------------
typedef CUresult (*EncodeFn)(CUtensorMap*, CUtensorMapDataType, cuuint32_t, void*,
                             const cuuint64_t*, const cuuint64_t*, const cuuint32_t*,
                             const cuuint32_t*, CUtensorMapInterleave, CUtensorMapSwizzle,
                             CUtensorMapL2promotion, CUtensorMapFloatOOBfill);

static void encode2d(EncodeFn fn, CUtensorMap* tm, void* ptr,
                     uint64_t cols, uint64_t rows, uint32_t boxc, uint32_t boxr){
  cuuint64_t dims[2]    = { cols, rows };
  cuuint64_t strides[1] = { cols * 2 };
  cuuint32_t box[2]     = { boxc, boxr };
  cuuint32_t estr[2]    = { 1, 1 };
  fn(tm, CU_TENSOR_MAP_DATA_TYPE_FLOAT16, 2, ptr, dims, strides, box, estr,
     CU_TENSOR_MAP_INTERLEAVE_NONE, CU_TENSOR_MAP_SWIZZLE_128B,
     CU_TENSOR_MAP_L2_PROMOTION_L2_128B, CU_TENSOR_MAP_FLOAT_OOB_FILL_NONE);
}

extern "C" void kernel_launch(void* const* d_in, const int* in_sizes, int n_in,
                              void* d_out, int out_size){
  const float* x  = (const float*)d_in[0];
  const float* rw = (const float*)d_in[1];
  const float* eb = (const float*)d_in[2];
  const float* gw = (const float*)d_in[3];
  const float* uw = (const float*)d_in[4];
  const float* dw = (const float*)d_in[5];
  const float* sg = (const float*)d_in[6];
  const float* su = (const float*)d_in[7];
  const float* sd = (const float*)d_in[8];
  float* out = (float*)d_out;
  (void)in_sizes; (void)n_in; (void)out_size;

  static bool setup_done = false;
  if (!setup_done){
    cudaFuncSetAttribute(gemm_gateup, cudaFuncAttributeMaxDynamicSharedMemorySize, SMEM_DYN);
    cudaFuncSetAttribute(gemm_down,   cudaFuncAttributeMaxDynamicSharedMemorySize, SMEM_DYN);
    void* fn = nullptr;
    cudaDriverEntryPointQueryResult qr;
    cudaGetDriverEntryPoint("cuTensorMapEncodeTiled", &fn, cudaEnableDefault, &qr);
    EncodeFn enc = (EncodeFn)fn;
    void *p_xs, *p_wg, *p_wu, *p_wd, *p_h;
    cudaGetSymbolAddress(&p_xs, g_xs);
    cudaGetSymbolAddress(&p_wg, g_wg);
    cudaGetSymbolAddress(&p_wu, g_wu);
    cudaGetSymbolAddress(&p_wd, g_wd);
    cudaGetSymbolAddress(&p_h,  g_h16);
    static CUtensorMap h_tm[5];
    encode2d(enc, &h_tm[0], p_xs, DIMX, (uint64_t)NEX*CAP,  64, 128);  // gu A
    encode2d(enc, &h_tm[1], p_wg, DIMX, (uint64_t)NEX*HIDX, 64, 64);   // gu gate
    encode2d(enc, &h_tm[2], p_wu, DIMX, (uint64_t)NEX*HIDX, 64, 64);   // gu up
    encode2d(enc, &h_tm[3], p_h,  HIDX, (uint64_t)NEX*CAP,  64, 128);  // dn A
    encode2d(enc, &h_tm[4], p_wd, HIDX, (uint64_t)NEX*DIMX, 64, 128);  // dn B
    cudaMemcpyToSymbolAsync(g_tmap, h_tm, 5*sizeof(CUtensorMap), 0,
                            cudaMemcpyHostToDevice, 0);
    setup_done = true;
  }

  {
    unsigned nb = (unsigned)(((size_t)NEX*HD/4 + 255)/256);
    cvt_all<<<dim3(nb,3), 256>>>(gw, uw, dw, sg, su, sd);
  }
  router_k<<<TTOK/8, 256>>>(x, rw, eb);
  scatter_x<<<TTOK, 128>>>(x);

  gemm_gateup<<<dim3(CAP/128, HIDX/64, NEX), 256, SMEM_DYN>>>();
  gemm_down  <<<dim3(DIMX/128, CAP/128, NEX), 256, SMEM_DYN>>>();
  gather_k<<<TTOK*1024/4/256, 256>>>((float4*)out);
}